// round 2
// baseline (speedup 1.0000x reference)
#include <cuda_runtime.h>
#include <cuda_bf16.h>
#include <cstdint>
#include <math.h>

// Problem shape (fixed)
#define BATCH 64
#define LEN   1024
#define DIM   1024
#define HID   1024
#define UNITS 1024
#define MROWS (BATCH * LEN)   // 65536

// GEMM tiling
#define BM 128
#define BN 128
#define BK 32
#define NTILES (UNITS / BN)   // 8
#define SMSTRIDE 36           // padded smem row stride (floats): bank = (4r + k) & 31 -> conflict-free

// Scratch (__device__ globals; no allocation allowed)
__device__ float g_w1t[(size_t)UNITS * DIM];        // W1 transposed [u][d], tf32-rounded (4 MB)
__device__ float g_projh[BATCH * UNITS];            // hidden @ W2 + b2 (256 KB)
__device__ float g_partial[(size_t)MROWS * NTILES]; // partial logits per (row, ntile) (2 MB)

__device__ __forceinline__ uint32_t f2tf32(float x) {
    uint32_t r;
    asm("cvt.rna.tf32.f32 %0, %1;" : "=r"(r) : "f"(x));
    return r;
}

__device__ __forceinline__ void mma_tf32(float c[4], const uint32_t a[4], const uint32_t b[2]) {
    asm volatile(
        "mma.sync.aligned.m16n8k8.row.col.f32.tf32.tf32.f32 "
        "{%0,%1,%2,%3}, {%4,%5,%6,%7}, {%8,%9}, {%0,%1,%2,%3};\n"
        : "+f"(c[0]), "+f"(c[1]), "+f"(c[2]), "+f"(c[3])
        : "r"(a[0]), "r"(a[1]), "r"(a[2]), "r"(a[3]), "r"(b[0]), "r"(b[1]));
}

// ---------------------------------------------------------------------------
// 1) Transpose W1 [D][U] -> g_w1t [U][D], rounded to tf32
// ---------------------------------------------------------------------------
__global__ void transpose_w1_kernel(const float* __restrict__ W1) {
    __shared__ float tile[32][33];
    int u = blockIdx.x * 32 + threadIdx.x;
    int d0 = blockIdx.y * 32;
#pragma unroll
    for (int j = 0; j < 32; j += 8)
        tile[threadIdx.y + j][threadIdx.x] = W1[(size_t)(d0 + threadIdx.y + j) * UNITS + u];
    __syncthreads();
    int dd = d0 + threadIdx.x;
    int u0 = blockIdx.x * 32;
#pragma unroll
    for (int j = 0; j < 32; j += 8)
        g_w1t[(size_t)(u0 + threadIdx.y + j) * DIM + dd] =
            __uint_as_float(f2tf32(tile[threadIdx.x][threadIdx.y + j]));
}

// ---------------------------------------------------------------------------
// 2) proj_h[b][u] = sum_h hidden[b][h] * W2[h][u] + b2[u]   (fp32 exact)
// ---------------------------------------------------------------------------
__global__ __launch_bounds__(256) void projh_kernel(const float* __restrict__ hidden,
                                                    const float* __restrict__ W2,
                                                    const float* __restrict__ b2) {
    __shared__ float sh[HID];
    int b = blockIdx.x, tid = threadIdx.x;
    for (int i = tid; i < HID; i += 256) sh[i] = hidden[(size_t)b * HID + i];
    __syncthreads();
    float a0 = 0.f, a1 = 0.f, a2 = 0.f, a3 = 0.f;
    for (int h = 0; h < HID; h++) {
        float hv = sh[h];
        const float* w = W2 + (size_t)h * UNITS;
        a0 += hv * w[tid];
        a1 += hv * w[tid + 256];
        a2 += hv * w[tid + 512];
        a3 += hv * w[tid + 768];
    }
    g_projh[(size_t)b * UNITS + tid]       = a0 + b2[tid];
    g_projh[(size_t)b * UNITS + tid + 256] = a1 + b2[tid + 256];
    g_projh[(size_t)b * UNITS + tid + 512] = a2 + b2[tid + 512];
    g_projh[(size_t)b * UNITS + tid + 768] = a3 + b2[tid + 768];
}

// ---------------------------------------------------------------------------
// 3) Fused: proj_f tile (tf32 MMA) -> tanh(+proj_h+b1) -> dot with V -> partial logits
//    grid: (NTILES, MROWS/BM), block: 256 threads = 8 warps (2 m x 4 n), warp tile 64x32
// ---------------------------------------------------------------------------
__global__ __launch_bounds__(256) void fused_gemm_kernel(const float* __restrict__ features,
                                                         const float* __restrict__ b1,
                                                         const float* __restrict__ V) {
    __shared__ float As[BM * SMSTRIDE];
    __shared__ float Bs[BN * SMSTRIDE];
    __shared__ float s_red[4][BM];
    __shared__ float s_add[BN];
    __shared__ float s_v[BN];

    const int tid = threadIdx.x;
    const int lane = tid & 31;
    const int warp = tid >> 5;
    const int wm = warp >> 2;   // 0..1
    const int wn = warp & 3;    // 0..3
    const int mtile = blockIdx.y;
    const int ntile = blockIdx.x;
    const size_t row0 = (size_t)mtile * BM;
    const int u0 = ntile * BN;
    const int b = mtile >> 3;   // 8 m-tiles per batch (L=1024 / BM=128)

    if (tid < BN) {
        s_add[tid] = g_projh[(size_t)b * UNITS + u0 + tid] + b1[u0 + tid];
        s_v[tid] = V[u0 + tid];
    }

    float acc[4][4][4];
#pragma unroll
    for (int mi = 0; mi < 4; mi++)
#pragma unroll
        for (int ni = 0; ni < 4; ni++)
#pragma unroll
            for (int j = 0; j < 4; j++) acc[mi][ni][j] = 0.f;

    const float* Ag = features + row0 * DIM;
    const float* Bg = g_w1t + (size_t)u0 * DIM;

    for (int k0 = 0; k0 < DIM; k0 += BK) {
        __syncthreads();
#pragma unroll
        for (int i = 0; i < 4; i++) {
            int idx = tid + i * 256;            // 0..1023
            int r = idx >> 3;                   // 0..127
            int c = (idx & 7) * 4;              // 0..28
            float4 va = *(const float4*)(Ag + (size_t)r * DIM + k0 + c);
            float4 vb = *(const float4*)(Bg + (size_t)r * DIM + k0 + c);
            float4 ra, rb;
            ra.x = __uint_as_float(f2tf32(va.x)); ra.y = __uint_as_float(f2tf32(va.y));
            ra.z = __uint_as_float(f2tf32(va.z)); ra.w = __uint_as_float(f2tf32(va.w));
            rb.x = __uint_as_float(f2tf32(vb.x)); rb.y = __uint_as_float(f2tf32(vb.y));
            rb.z = __uint_as_float(f2tf32(vb.z)); rb.w = __uint_as_float(f2tf32(vb.w));
            *(float4*)(&As[r * SMSTRIDE + c]) = ra;
            *(float4*)(&Bs[r * SMSTRIDE + c]) = rb;
        }
        __syncthreads();

#pragma unroll
        for (int ks = 0; ks < 4; ks++) {
            const int kk = ks * 8 + (lane & 3);
            uint32_t afr[4][4], bfr[4][2];
#pragma unroll
            for (int mi = 0; mi < 4; mi++) {
                int r = wm * 64 + mi * 16 + (lane >> 2);
                afr[mi][0] = __float_as_uint(As[r * SMSTRIDE + kk]);
                afr[mi][1] = __float_as_uint(As[(r + 8) * SMSTRIDE + kk]);
                afr[mi][2] = __float_as_uint(As[r * SMSTRIDE + kk + 4]);
                afr[mi][3] = __float_as_uint(As[(r + 8) * SMSTRIDE + kk + 4]);
            }
#pragma unroll
            for (int ni = 0; ni < 4; ni++) {
                int n = wn * 32 + ni * 8 + (lane >> 2);
                bfr[ni][0] = __float_as_uint(Bs[n * SMSTRIDE + kk]);
                bfr[ni][1] = __float_as_uint(Bs[n * SMSTRIDE + kk + 4]);
            }
#pragma unroll
            for (int mi = 0; mi < 4; mi++)
#pragma unroll
                for (int ni = 0; ni < 4; ni++)
                    mma_tf32(acc[mi][ni], afr[mi], bfr[ni]);
        }
    }

    // Epilogue: score = tanh(acc + proj_h + b1); partial += V[u]*score; reduce over BN cols
#pragma unroll
    for (int mi = 0; mi < 4; mi++) {
        float sum0 = 0.f, sum1 = 0.f;
#pragma unroll
        for (int ni = 0; ni < 4; ni++) {
            int c = wn * 32 + ni * 8 + 2 * (lane & 3);
            float add0 = s_add[c], add1 = s_add[c + 1];
            float v0 = s_v[c], v1 = s_v[c + 1];
            sum0 += v0 * tanhf(acc[mi][ni][0] + add0) + v1 * tanhf(acc[mi][ni][1] + add1);
            sum1 += v0 * tanhf(acc[mi][ni][2] + add0) + v1 * tanhf(acc[mi][ni][3] + add1);
        }
        sum0 += __shfl_xor_sync(0xffffffff, sum0, 1);
        sum0 += __shfl_xor_sync(0xffffffff, sum0, 2);
        sum1 += __shfl_xor_sync(0xffffffff, sum1, 1);
        sum1 += __shfl_xor_sync(0xffffffff, sum1, 2);
        if ((lane & 3) == 0) {
            int r = wm * 64 + mi * 16 + (lane >> 2);
            s_red[wn][r] = sum0;
            s_red[wn][r + 8] = sum1;
        }
    }
    __syncthreads();
    if (tid < BM) {
        float part = (s_red[0][tid] + s_red[1][tid]) + (s_red[2][tid] + s_red[3][tid]);
        g_partial[(row0 + tid) * NTILES + ntile] = part;
    }
}

// ---------------------------------------------------------------------------
// 4) Softmax over L per batch; writes attention weights into d_out half 2
// ---------------------------------------------------------------------------
__global__ __launch_bounds__(256) void softmax_kernel(const float* __restrict__ bV,
                                                      float* __restrict__ out_w) {
    __shared__ float sl[LEN];
    __shared__ float sred[256];
    int b = blockIdx.x, tid = threadIdx.x;
    float bv = bV[0];
    float lmax = -1e30f;
    for (int i = tid; i < LEN; i += 256) {
        const float* p = g_partial + (size_t)(b * LEN + i) * NTILES;
        float s = ((p[0] + p[1]) + (p[2] + p[3])) + ((p[4] + p[5]) + (p[6] + p[7])) + bv;
        sl[i] = s;
        lmax = fmaxf(lmax, s);
    }
    sred[tid] = lmax;
    __syncthreads();
    for (int s = 128; s > 0; s >>= 1) {
        if (tid < s) sred[tid] = fmaxf(sred[tid], sred[tid + s]);
        __syncthreads();
    }
    float mx = sred[0];
    __syncthreads();
    float lsum = 0.f;
    for (int i = tid; i < LEN; i += 256) {
        float e = expf(sl[i] - mx);
        sl[i] = e;
        lsum += e;
    }
    sred[tid] = lsum;
    __syncthreads();
    for (int s = 128; s > 0; s >>= 1) {
        if (tid < s) sred[tid] += sred[tid + s];
        __syncthreads();
    }
    float inv = 1.0f / sred[0];
    for (int i = tid; i < LEN; i += 256)
        out_w[(size_t)b * LEN + i] = sl[i] * inv;
}

// ---------------------------------------------------------------------------
// 5) context[b][d] = sum_l w[b][l] * features[b][l][d]   (fp32, memory bound)
// ---------------------------------------------------------------------------
__global__ __launch_bounds__(256) void context_kernel(const float* __restrict__ features,
                                                      const float* __restrict__ w,
                                                      float* __restrict__ out) {
    __shared__ float sw[LEN];
    int b = blockIdx.y, chunk = blockIdx.x, tid = threadIdx.x;
    for (int i = tid; i < LEN; i += 256) sw[i] = w[(size_t)b * LEN + i];
    __syncthreads();
    int d = chunk * 256 + tid;
    const float* f = features + (size_t)b * LEN * DIM + d;
    float a0 = 0.f, a1 = 0.f, a2 = 0.f, a3 = 0.f;
    for (int l = 0; l < LEN; l += 4) {
        a0 += sw[l]     * f[(size_t)l * DIM];
        a1 += sw[l + 1] * f[(size_t)(l + 1) * DIM];
        a2 += sw[l + 2] * f[(size_t)(l + 2) * DIM];
        a3 += sw[l + 3] * f[(size_t)(l + 3) * DIM];
    }
    out[(size_t)b * DIM + d] = (a0 + a1) + (a2 + a3);
}

// ---------------------------------------------------------------------------
extern "C" void kernel_launch(void* const* d_in, const int* in_sizes, int n_in,
                              void* d_out, int out_size) {
    const float* features = (const float*)d_in[0];  // [B, L, D]
    const float* hidden   = (const float*)d_in[1];  // [B, H]
    const float* W1       = (const float*)d_in[2];  // [D, U]
    const float* b1       = (const float*)d_in[3];  // [U]
    const float* W2       = (const float*)d_in[4];  // [H, U]
    const float* b2       = (const float*)d_in[5];  // [U]
    const float* V        = (const float*)d_in[6];  // [U, 1]
    const float* bV       = (const float*)d_in[7];  // [1]

    float* out_ctx = (float*)d_out;                     // [B, D]
    float* out_w   = (float*)d_out + BATCH * DIM;       // [B, L, 1]

    transpose_w1_kernel<<<dim3(32, 32), dim3(32, 8)>>>(W1);
    projh_kernel<<<BATCH, 256>>>(hidden, W2, b2);
    fused_gemm_kernel<<<dim3(NTILES, MROWS / BM), 256>>>(features, b1, V);
    softmax_kernel<<<BATCH, 256>>>(bV, out_w);
    context_kernel<<<dim3(DIM / 256, BATCH), 256>>>(features, out_w, out_ctx);
}

// round 4
// speedup vs baseline: 1.3293x; 1.3293x over previous
#include <cuda_runtime.h>
#include <cuda_bf16.h>
#include <cstdint>
#include <math.h>

// Problem shape (fixed)
#define BATCH 64
#define LEN   1024
#define DIM   1024
#define HID   1024
#define UNITS 1024
#define MROWS (BATCH * LEN)   // 65536

// GEMM tiling (mma.sync tf32 path; tcgen05 unavailable: PTX target lacks 'a')
#define BM 128
#define BN 256
#define BK 32                 // floats per k-chunk = 128 bytes/row
#define KT (DIM / BK)         // 32
#define NTILES (UNITS / BN)   // 4
#define STAGES 3
#define STAGE_A_BYTES (BM * 128)                       // 16384
#define STAGE_B_BYTES (BN * 128)                       // 32768
#define STAGE_BYTES   (STAGE_A_BYTES + STAGE_B_BYTES)  // 49152
#define DYN_SMEM (STAGES * STAGE_BYTES)                // 147456

// Scratch (__device__ globals; no allocation allowed)
__device__ float g_w1t[(size_t)UNITS * DIM];        // W1 transposed [u][d], tf32-rounded
__device__ float g_projh[BATCH * UNITS];            // hidden @ W2 + b2
__device__ float g_partial[(size_t)MROWS * NTILES]; // partial logits per (row, ntile)

// ---------------------------------------------------------------------------
// helpers
// ---------------------------------------------------------------------------
__device__ __forceinline__ uint32_t smem_u32(const void* p) {
    uint32_t a;
    asm("{ .reg .u64 t; cvta.to.shared.u64 t, %1; cvt.u32.u64 %0, t; }" : "=r"(a) : "l"(p));
    return a;
}

__device__ __forceinline__ uint32_t f2tf32(float x) {
    uint32_t r;
    asm("cvt.rna.tf32.f32 %0, %1;" : "=r"(r) : "f"(x));
    return r;
}

#define CP_ASYNC16(dst, src) \
    asm volatile("cp.async.cg.shared.global [%0], [%1], 16;" :: "r"(dst), "l"(src))
#define CP_COMMIT() asm volatile("cp.async.commit_group;" ::: "memory")
#define CP_WAIT1()  asm volatile("cp.async.wait_group 1;" ::: "memory")
#define CP_WAIT0()  asm volatile("cp.async.wait_group 0;" ::: "memory")

#define LDSM_X4(r, addr)                                                        \
    asm volatile("ldmatrix.sync.aligned.m8n8.x4.shared.b16 {%0,%1,%2,%3}, [%4];" \
                 : "=r"((r)[0]), "=r"((r)[1]), "=r"((r)[2]), "=r"((r)[3])        \
                 : "r"(addr))

__device__ __forceinline__ void mma_tf32(float c[4], const uint32_t a[4],
                                         uint32_t b0, uint32_t b1) {
    asm volatile(
        "mma.sync.aligned.m16n8k8.row.col.f32.tf32.tf32.f32 "
        "{%0,%1,%2,%3}, {%4,%5,%6,%7}, {%8,%9}, {%0,%1,%2,%3};\n"
        : "+f"(c[0]), "+f"(c[1]), "+f"(c[2]), "+f"(c[3])
        : "r"(a[0]), "r"(a[1]), "r"(a[2]), "r"(a[3]), "r"(b0), "r"(b1));
}

__device__ __forceinline__ float tanh_fast(float x) {
    // 1 - 2/(exp(2x)+1); saturates correctly for large |x|
    float e = __expf(2.0f * x);
    return 1.0f - __fdividef(2.0f, e + 1.0f);
}

// ---------------------------------------------------------------------------
// 1) Transpose W1 [D][U] -> g_w1t [U][D], rounded to tf32 (rna)
// ---------------------------------------------------------------------------
__global__ void transpose_w1_kernel(const float* __restrict__ W1) {
    __shared__ float tile[32][33];
    int u = blockIdx.x * 32 + threadIdx.x;
    int d0 = blockIdx.y * 32;
#pragma unroll
    for (int j = 0; j < 32; j += 8)
        tile[threadIdx.y + j][threadIdx.x] = W1[(size_t)(d0 + threadIdx.y + j) * UNITS + u];
    __syncthreads();
    int dd = d0 + threadIdx.x;
    int u0 = blockIdx.x * 32;
#pragma unroll
    for (int j = 0; j < 32; j += 8)
        g_w1t[(size_t)(u0 + threadIdx.y + j) * DIM + dd] =
            __uint_as_float(f2tf32(tile[threadIdx.x][threadIdx.y + j]));
}

// ---------------------------------------------------------------------------
// 2) proj_h[b][u] = hidden[b] @ W2 + b2   (fp32 exact)
// ---------------------------------------------------------------------------
__global__ __launch_bounds__(256) void projh_kernel(const float* __restrict__ hidden,
                                                    const float* __restrict__ W2,
                                                    const float* __restrict__ b2) {
    __shared__ float sh[HID];
    int b = blockIdx.x, tid = threadIdx.x;
    for (int i = tid; i < HID; i += 256) sh[i] = hidden[(size_t)b * HID + i];
    __syncthreads();
    float a0 = 0.f, a1 = 0.f, a2 = 0.f, a3 = 0.f;
    for (int h = 0; h < HID; h++) {
        float hv = sh[h];
        const float* w = W2 + (size_t)h * UNITS;
        a0 += hv * w[tid];
        a1 += hv * w[tid + 256];
        a2 += hv * w[tid + 512];
        a3 += hv * w[tid + 768];
    }
    g_projh[(size_t)b * UNITS + tid]       = a0 + b2[tid];
    g_projh[(size_t)b * UNITS + tid + 256] = a1 + b2[tid + 256];
    g_projh[(size_t)b * UNITS + tid + 512] = a2 + b2[tid + 512];
    g_projh[(size_t)b * UNITS + tid + 768] = a3 + b2[tid + 768];
}

// ---------------------------------------------------------------------------
// 3) Fused GEMM: cp.async 3-stage pipeline + ldmatrix + mma.tf32
//    grid (NTILES, MROWS/BM) = (4, 512); 512 threads = 16 warps (2m x 8n)
//    warp tile 64x32; epilogue fuses tanh(+proj_h+b1) and the V-dot.
// ---------------------------------------------------------------------------
__global__ __launch_bounds__(512, 1) void fused_gemm_mma(const float* __restrict__ features,
                                                         const float* __restrict__ b1,
                                                         const float* __restrict__ V) {
    extern __shared__ char dsmem_raw[];
    __shared__ float s_red[8][BM];
    __shared__ float s_add[BN];
    __shared__ float s_v[BN];

    const int tid  = threadIdx.x;
    const int lane = tid & 31;
    const int warp = tid >> 5;          // 0..15
    const int wm   = warp >> 3;         // 0..1
    const int wn   = warp & 7;          // 0..7
    const int ntile = blockIdx.x;
    const int mtile = blockIdx.y;
    const size_t row0 = (size_t)mtile * BM;
    const int u0 = ntile * BN;
    const int b = mtile >> 3;           // LEN/BM = 8 m-tiles per batch

    const uint32_t smem0 = smem_u32(dsmem_raw);  // 1024-aligned (extern smem is 16B.. use 128B rows; base alignment of dynamic smem is 16B min but typically 1KB; enforce via mask)
    // (dynamic smem base is at least 128B aligned in practice; swizzle only needs 128B row alignment within the 1024-stage blocks which start at multiples of 48KB from base)

    if (tid < BN) {
        s_add[tid] = g_projh[(size_t)b * UNITS + u0 + tid] + b1[u0 + tid];
        s_v[tid]   = V[u0 + tid];
    }

    float acc[4][4][4];
#pragma unroll
    for (int mi = 0; mi < 4; mi++)
#pragma unroll
        for (int ni = 0; ni < 4; ni++)
#pragma unroll
            for (int j = 0; j < 4; j++) acc[mi][ni][j] = 0.f;

    const float* Ag = features + row0 * DIM;
    const float* Bg = g_w1t + (size_t)u0 * DIM;

    // loader constants (512 threads, 8 threads/row, 16B each)
    const int lrow = tid >> 3;                 // 0..63
    const int lcolf = (tid & 7) * 4;           // float col 0..28
    const uint32_t lsw = ((tid & 7) * 16) ^ ((uint32_t)(lrow & 7) << 4);

    // ldmatrix per-lane constants
    const uint32_t xorp = (uint32_t)(lane & 7) << 4;
    const uint32_t aRowB = (uint32_t)(wm * 64 + ((lane >> 3) & 1) * 8 + (lane & 7)) * 128;
    const uint32_t aColB = (uint32_t)(lane >> 4) * 16;
    const uint32_t bRowB = (uint32_t)(wn * 32 + ((lane >> 4) & 1) * 8 + (lane & 7)) * 128;
    const uint32_t bColB = (uint32_t)((lane >> 3) & 1) * 16;

    // ---- stage loader ----
    auto load_stage = [&](int itL, int slot) {
        const uint32_t sA = smem0 + slot * STAGE_BYTES;
        const uint32_t sB = sA + STAGE_A_BYTES;
        const int k0 = itL * BK;
#pragma unroll
        for (int p = 0; p < 2; p++) {          // A: 128 rows
            int r = lrow + p * 64;
            CP_ASYNC16(sA + (uint32_t)r * 128 + lsw, Ag + (size_t)r * DIM + k0 + lcolf);
        }
#pragma unroll
        for (int p = 0; p < 4; p++) {          // B: 256 rows
            int r = lrow + p * 64;
            CP_ASYNC16(sB + (uint32_t)r * 128 + lsw, Bg + (size_t)r * DIM + k0 + lcolf);
        }
    };

    load_stage(0, 0); CP_COMMIT();
    load_stage(1, 1); CP_COMMIT();

    int loadIt = 2, loadSlot = 2, compSlot = 0;
#pragma unroll 1
    for (int it = 0; it < KT; it++) {
        if (loadIt < KT) load_stage(loadIt, loadSlot);
        CP_COMMIT();                // (possibly empty group keeps counting consistent)
        CP_WAIT1();                 // stage `it` resident
        __syncthreads();

        const uint32_t sA = smem0 + compSlot * STAGE_BYTES;
        const uint32_t sB = sA + STAGE_A_BYTES;
#pragma unroll
        for (int ks = 0; ks < 4; ks++) {
            const uint32_t ac = ((uint32_t)(ks * 32) + aColB) ^ xorp;
            const uint32_t bc = ((uint32_t)(ks * 32) + bColB) ^ xorp;
            uint32_t afr[4][4];
#pragma unroll
            for (int mi = 0; mi < 4; mi++)
                LDSM_X4(afr[mi], sA + aRowB + (uint32_t)mi * 2048 + ac);
            uint32_t bfr[2][4];
#pragma unroll
            for (int p = 0; p < 2; p++)
                LDSM_X4(bfr[p], sB + bRowB + (uint32_t)p * 2048 + bc);
#pragma unroll
            for (int mi = 0; mi < 4; mi++) {
#pragma unroll
                for (int p = 0; p < 2; p++) {
                    mma_tf32(acc[mi][2 * p],     afr[mi], bfr[p][0], bfr[p][1]);
                    mma_tf32(acc[mi][2 * p + 1], afr[mi], bfr[p][2], bfr[p][3]);
                }
            }
        }
        __syncthreads();
        loadIt++;
        loadSlot = (loadSlot == STAGES - 1) ? 0 : loadSlot + 1;
        compSlot = (compSlot == STAGES - 1) ? 0 : compSlot + 1;
    }
    CP_WAIT0();

    // ---- epilogue: tanh(acc + proj_h + b1) . V, reduce over BN ----
#pragma unroll
    for (int mi = 0; mi < 4; mi++) {
        float sum0 = 0.f, sum1 = 0.f;
#pragma unroll
        for (int ni = 0; ni < 4; ni++) {
            int c = wn * 32 + ni * 8 + 2 * (lane & 3);
            float add0 = s_add[c], add1 = s_add[c + 1];
            float v0 = s_v[c], v1 = s_v[c + 1];
            sum0 += v0 * tanh_fast(acc[mi][ni][0] + add0) + v1 * tanh_fast(acc[mi][ni][1] + add1);
            sum1 += v0 * tanh_fast(acc[mi][ni][2] + add0) + v1 * tanh_fast(acc[mi][ni][3] + add1);
        }
        sum0 += __shfl_xor_sync(0xffffffff, sum0, 1);
        sum0 += __shfl_xor_sync(0xffffffff, sum0, 2);
        sum1 += __shfl_xor_sync(0xffffffff, sum1, 1);
        sum1 += __shfl_xor_sync(0xffffffff, sum1, 2);
        if ((lane & 3) == 0) {
            int r = wm * 64 + mi * 16 + (lane >> 2);
            s_red[wn][r]     = sum0;
            s_red[wn][r + 8] = sum1;
        }
    }
    __syncthreads();
    if (tid < BM) {
        float part = ((s_red[0][tid] + s_red[1][tid]) + (s_red[2][tid] + s_red[3][tid])) +
                     ((s_red[4][tid] + s_red[5][tid]) + (s_red[6][tid] + s_red[7][tid]));
        g_partial[(row0 + tid) * NTILES + ntile] = part;
    }
}

// ---------------------------------------------------------------------------
// 4) Softmax over L per batch; writes attention weights into d_out half 2
// ---------------------------------------------------------------------------
__global__ __launch_bounds__(256) void softmax_kernel(const float* __restrict__ bV,
                                                      float* __restrict__ out_w) {
    __shared__ float sl[LEN];
    __shared__ float sred[256];
    int b = blockIdx.x, tid = threadIdx.x;
    float bv = bV[0];
    float lmax = -1e30f;
    for (int i = tid; i < LEN; i += 256) {
        const float* p = g_partial + (size_t)(b * LEN + i) * NTILES;
        float s = (p[0] + p[1]) + (p[2] + p[3]) + bv;
        sl[i] = s;
        lmax = fmaxf(lmax, s);
    }
    sred[tid] = lmax;
    __syncthreads();
    for (int s = 128; s > 0; s >>= 1) {
        if (tid < s) sred[tid] = fmaxf(sred[tid], sred[tid + s]);
        __syncthreads();
    }
    float mx = sred[0];
    __syncthreads();
    float lsum = 0.f;
    for (int i = tid; i < LEN; i += 256) {
        float e = expf(sl[i] - mx);
        sl[i] = e;
        lsum += e;
    }
    sred[tid] = lsum;
    __syncthreads();
    for (int s = 128; s > 0; s >>= 1) {
        if (tid < s) sred[tid] += sred[tid + s];
        __syncthreads();
    }
    float inv = 1.0f / sred[0];
    for (int i = tid; i < LEN; i += 256)
        out_w[(size_t)b * LEN + i] = sl[i] * inv;
}

// ---------------------------------------------------------------------------
// 5) context[b][d] = sum_l w[b][l] * features[b][l][d]
// ---------------------------------------------------------------------------
__global__ __launch_bounds__(256) void context_kernel(const float* __restrict__ features,
                                                      const float* __restrict__ w,
                                                      float* __restrict__ out) {
    __shared__ float sw[LEN];
    int b = blockIdx.y, chunk = blockIdx.x, tid = threadIdx.x;
    for (int i = tid; i < LEN; i += 256) sw[i] = w[(size_t)b * LEN + i];
    __syncthreads();
    int d = chunk * 256 + tid;
    const float* f = features + (size_t)b * LEN * DIM + d;
    float a0 = 0.f, a1 = 0.f, a2 = 0.f, a3 = 0.f;
    for (int l = 0; l < LEN; l += 4) {
        a0 += sw[l]     * f[(size_t)l * DIM];
        a1 += sw[l + 1] * f[(size_t)(l + 1) * DIM];
        a2 += sw[l + 2] * f[(size_t)(l + 2) * DIM];
        a3 += sw[l + 3] * f[(size_t)(l + 3) * DIM];
    }
    out[(size_t)b * DIM + d] = (a0 + a1) + (a2 + a3);
}

// ---------------------------------------------------------------------------
extern "C" void kernel_launch(void* const* d_in, const int* in_sizes, int n_in,
                              void* d_out, int out_size) {
    const float* features = (const float*)d_in[0];  // [B, L, D]
    const float* hidden   = (const float*)d_in[1];  // [B, H]
    const float* W1       = (const float*)d_in[2];  // [D, U]
    const float* b1       = (const float*)d_in[3];  // [U]
    const float* W2       = (const float*)d_in[4];  // [H, U]
    const float* b2       = (const float*)d_in[5];  // [U]
    const float* V        = (const float*)d_in[6];  // [U, 1]
    const float* bV       = (const float*)d_in[7];  // [1]

    float* out_ctx = (float*)d_out;                 // [B, D]
    float* out_w   = (float*)d_out + BATCH * DIM;   // [B, L, 1]

    static bool attr_set = false;
    if (!attr_set) {
        cudaFuncSetAttribute(fused_gemm_mma, cudaFuncAttributeMaxDynamicSharedMemorySize, DYN_SMEM);
        attr_set = true;
    }

    transpose_w1_kernel<<<dim3(32, 32), dim3(32, 8)>>>(W1);
    projh_kernel<<<BATCH, 256>>>(hidden, W2, b2);
    fused_gemm_mma<<<dim3(NTILES, MROWS / BM), 512, DYN_SMEM>>>(features, b1, V);
    softmax_kernel<<<BATCH, 256>>>(bV, out_w);
    context_kernel<<<dim3(DIM / 256, BATCH), 256>>>(features, out_w, out_ctx);
}

// round 5
// speedup vs baseline: 1.4819x; 1.1148x over previous
#include <cuda_runtime.h>
#include <cuda_bf16.h>
#include <cstdint>
#include <math.h>

// Problem shape (fixed)
#define BATCH 64
#define LEN   1024
#define DIM   1024
#define HID   1024
#define UNITS 1024
#define MROWS (BATCH * LEN)   // 65536

// GEMM tiling (mma.sync tf32; tcgen05 unavailable — PTX target lacks 'a')
#define BM 128
#define BN 256
#define BK 32                 // floats per k-chunk = 128 bytes/row
#define KT (DIM / BK)         // 32
#define NTILES (UNITS / BN)   // 4
#define STAGES 3
#define STAGE_A_BYTES (BM * 128)                       // 16384
#define STAGE_B_BYTES (BN * 128)                       // 32768
#define STAGE_BYTES   (STAGE_A_BYTES + STAGE_B_BYTES)  // 49152
#define DYN_SMEM (STAGES * STAGE_BYTES)                // 147456

// Scratch (__device__ globals; no allocation allowed)
__device__ float g_w1t[(size_t)UNITS * DIM];        // W1 transposed [u][d], tf32-rounded
__device__ float g_projh[BATCH * UNITS];            // hidden @ W2 + b2
__device__ float g_partial[(size_t)MROWS * NTILES]; // partial logits per (row, ntile)

// ---------------------------------------------------------------------------
// helpers
// ---------------------------------------------------------------------------
__device__ __forceinline__ uint32_t smem_u32(const void* p) {
    uint32_t a;
    asm("{ .reg .u64 t; cvta.to.shared.u64 t, %1; cvt.u32.u64 %0, t; }" : "=r"(a) : "l"(p));
    return a;
}

__device__ __forceinline__ uint32_t f2tf32(float x) {
    uint32_t r;
    asm("cvt.rna.tf32.f32 %0, %1;" : "=r"(r) : "f"(x));
    return r;
}

#define CP_ASYNC16(dst, src) \
    asm volatile("cp.async.cg.shared.global [%0], [%1], 16;" :: "r"(dst), "l"(src))
#define CP_COMMIT() asm volatile("cp.async.commit_group;" ::: "memory")
#define CP_WAIT1()  asm volatile("cp.async.wait_group 1;" ::: "memory")
#define CP_WAIT0()  asm volatile("cp.async.wait_group 0;" ::: "memory")

#define LDSM_X4(r, addr)                                                        \
    asm volatile("ldmatrix.sync.aligned.m8n8.x4.shared.b16 {%0,%1,%2,%3}, [%4];" \
                 : "=r"((r)[0]), "=r"((r)[1]), "=r"((r)[2]), "=r"((r)[3])        \
                 : "r"(addr))

__device__ __forceinline__ void mma_tf32(float c[4], const uint32_t a[4],
                                         uint32_t b0, uint32_t b1) {
    asm volatile(
        "mma.sync.aligned.m16n8k8.row.col.f32.tf32.tf32.f32 "
        "{%0,%1,%2,%3}, {%4,%5,%6,%7}, {%8,%9}, {%0,%1,%2,%3};\n"
        : "+f"(c[0]), "+f"(c[1]), "+f"(c[2]), "+f"(c[3])
        : "r"(a[0]), "r"(a[1]), "r"(a[2]), "r"(a[3]), "r"(b0), "r"(b1));
}

__device__ __forceinline__ float tanh_fast(float x) {
    float e = __expf(2.0f * x);
    return 1.0f - __fdividef(2.0f, e + 1.0f);
}

// ---------------------------------------------------------------------------
// 1) Transpose W1 [D][U] -> g_w1t [U][D], rounded to tf32 (rna)
// ---------------------------------------------------------------------------
__global__ void transpose_w1_kernel(const float* __restrict__ W1) {
    __shared__ float tile[32][33];
    int u = blockIdx.x * 32 + threadIdx.x;
    int d0 = blockIdx.y * 32;
#pragma unroll
    for (int j = 0; j < 32; j += 8)
        tile[threadIdx.y + j][threadIdx.x] = W1[(size_t)(d0 + threadIdx.y + j) * UNITS + u];
    __syncthreads();
    int dd = d0 + threadIdx.x;
    int u0 = blockIdx.x * 32;
#pragma unroll
    for (int j = 0; j < 32; j += 8)
        g_w1t[(size_t)(u0 + threadIdx.y + j) * DIM + dd] =
            __uint_as_float(f2tf32(tile[threadIdx.x][threadIdx.y + j]));
}

// ---------------------------------------------------------------------------
// 2) proj_h = hidden @ W2 + b2 — tiled so W2 is read exactly once (4 MB)
//    grid 16 CTAs x 64 u-cols; 512 threads; fp32 exact
// ---------------------------------------------------------------------------
__global__ __launch_bounds__(512) void projh_kernel(const float* __restrict__ hidden,
                                                    const float* __restrict__ W2,
                                                    const float* __restrict__ b2) {
    __shared__ float sh[64][65];  // [b][h-chunk]
    __shared__ float sw[64][65];  // [h-chunk][u]
    const int tid = threadIdx.x;
    const int u0 = blockIdx.x * 64;
    const int uu = tid & 63;
    const int bb = (tid >> 6) * 8;
    float acc[8] = {0.f, 0.f, 0.f, 0.f, 0.f, 0.f, 0.f, 0.f};

    for (int hc = 0; hc < HID / 64; hc++) {
        const int h0 = hc * 64;
#pragma unroll
        for (int i = 0; i < 8; i++) {
            int idx = tid + i * 512;
            int b = idx >> 6, h = idx & 63;
            sh[b][h] = hidden[(size_t)b * HID + h0 + h];
        }
#pragma unroll
        for (int i = 0; i < 8; i++) {
            int idx = tid + i * 512;
            int h = idx >> 6, u = idx & 63;
            sw[h][u] = W2[(size_t)(h0 + h) * UNITS + u0 + u];
        }
        __syncthreads();
#pragma unroll 16
        for (int h = 0; h < 64; h++) {
            float w = sw[h][uu];
#pragma unroll
            for (int j = 0; j < 8; j++)
                acc[j] += sh[bb + j][h] * w;
        }
        __syncthreads();
    }
    float bias = b2[u0 + uu];
#pragma unroll
    for (int j = 0; j < 8; j++)
        g_projh[(size_t)(bb + j) * UNITS + u0 + uu] = acc[j] + bias;
}

// ---------------------------------------------------------------------------
// 3) Fused GEMM: cp.async 3-stage + ldmatrix + mma.tf32
//    grid (NTILES, MROWS/BM) = (4, 512); 256 threads = 8 warps (2m x 4n)
//    warp tile 64x64 (128 acc regs) -> halves smem fragment traffic vs 64x32
// ---------------------------------------------------------------------------
__global__ __launch_bounds__(256, 1) void fused_gemm_mma(const float* __restrict__ features,
                                                         const float* __restrict__ b1,
                                                         const float* __restrict__ V) {
    extern __shared__ char dsmem_raw[];
    __shared__ float s_red[4][BM];
    __shared__ float s_add[BN];
    __shared__ float s_v[BN];

    const int tid  = threadIdx.x;
    const int lane = tid & 31;
    const int warp = tid >> 5;          // 0..7
    const int wm   = warp >> 2;         // 0..1
    const int wn   = warp & 3;          // 0..3
    const int ntile = blockIdx.x;
    const int mtile = blockIdx.y;
    const size_t row0 = (size_t)mtile * BM;
    const int u0 = ntile * BN;
    const int b = mtile >> 3;           // LEN/BM = 8 m-tiles per batch

    const uint32_t smem0 = smem_u32(dsmem_raw);

    s_add[tid]       = g_projh[(size_t)b * UNITS + u0 + tid] + b1[u0 + tid];
    s_v[tid]         = V[u0 + tid];

    float acc[4][8][4];
#pragma unroll
    for (int mi = 0; mi < 4; mi++)
#pragma unroll
        for (int ni = 0; ni < 8; ni++)
#pragma unroll
            for (int j = 0; j < 4; j++) acc[mi][ni][j] = 0.f;

    const float* Ag = features + row0 * DIM;
    const float* Bg = g_w1t + (size_t)u0 * DIM;

    // loader constants (256 threads, 8 threads/row, 16B each)
    const int lrow  = tid >> 3;                // 0..31
    const int lcolf = (tid & 7) * 4;
    const uint32_t lsw = ((uint32_t)(tid & 7) * 16) ^ ((uint32_t)(lrow & 7) << 4);

    // ldmatrix per-lane constants
    const uint32_t xorp  = (uint32_t)(lane & 7) << 4;
    const uint32_t aRowB = (uint32_t)(wm * 64 + ((lane >> 3) & 1) * 8 + (lane & 7)) * 128;
    const uint32_t aColB = (uint32_t)(lane >> 4) * 16;
    const uint32_t bRowB = (uint32_t)(wn * 64 + ((lane >> 4) & 1) * 8 + (lane & 7)) * 128;
    const uint32_t bColB = (uint32_t)((lane >> 3) & 1) * 16;

    auto load_stage = [&](int itL, int slot) {
        const uint32_t sA = smem0 + slot * STAGE_BYTES;
        const uint32_t sB = sA + STAGE_A_BYTES;
        const int k0 = itL * BK;
#pragma unroll
        for (int p = 0; p < 4; p++) {          // A: 128 rows
            int r = lrow + p * 32;
            CP_ASYNC16(sA + (uint32_t)r * 128 + lsw, Ag + (size_t)r * DIM + k0 + lcolf);
        }
#pragma unroll
        for (int p = 0; p < 8; p++) {          // B: 256 rows
            int r = lrow + p * 32;
            CP_ASYNC16(sB + (uint32_t)r * 128 + lsw, Bg + (size_t)r * DIM + k0 + lcolf);
        }
    };

    load_stage(0, 0); CP_COMMIT();
    load_stage(1, 1); CP_COMMIT();

    int loadIt = 2, loadSlot = 2, compSlot = 0;
#pragma unroll 1
    for (int it = 0; it < KT; it++) {
        if (loadIt < KT) load_stage(loadIt, loadSlot);
        CP_COMMIT();
        CP_WAIT1();
        __syncthreads();

        const uint32_t sA = smem0 + compSlot * STAGE_BYTES;
        const uint32_t sB = sA + STAGE_A_BYTES;
#pragma unroll
        for (int ks = 0; ks < 4; ks++) {
            const uint32_t ac = ((uint32_t)(ks * 32) + aColB) ^ xorp;
            const uint32_t bc = ((uint32_t)(ks * 32) + bColB) ^ xorp;
            uint32_t afr[4][4];
#pragma unroll
            for (int mi = 0; mi < 4; mi++)
                LDSM_X4(afr[mi], sA + aRowB + (uint32_t)mi * 2048 + ac);
            uint32_t bfr[4][4];
#pragma unroll
            for (int p = 0; p < 4; p++)
                LDSM_X4(bfr[p], sB + bRowB + (uint32_t)p * 2048 + bc);
#pragma unroll
            for (int mi = 0; mi < 4; mi++) {
#pragma unroll
                for (int p = 0; p < 4; p++) {
                    mma_tf32(acc[mi][2 * p],     afr[mi], bfr[p][0], bfr[p][1]);
                    mma_tf32(acc[mi][2 * p + 1], afr[mi], bfr[p][2], bfr[p][3]);
                }
            }
        }
        __syncthreads();
        loadIt++;
        loadSlot = (loadSlot == STAGES - 1) ? 0 : loadSlot + 1;
        compSlot = (compSlot == STAGES - 1) ? 0 : compSlot + 1;
    }
    CP_WAIT0();

    // ---- epilogue: tanh(acc + proj_h + b1) . V, reduce over BN ----
#pragma unroll
    for (int mi = 0; mi < 4; mi++) {
        float sum0 = 0.f, sum1 = 0.f;
#pragma unroll
        for (int ni = 0; ni < 8; ni++) {
            int c = wn * 64 + ni * 8 + 2 * (lane & 3);
            float add0 = s_add[c], add1 = s_add[c + 1];
            float v0 = s_v[c], v1 = s_v[c + 1];
            sum0 += v0 * tanh_fast(acc[mi][ni][0] + add0) + v1 * tanh_fast(acc[mi][ni][1] + add1);
            sum1 += v0 * tanh_fast(acc[mi][ni][2] + add0) + v1 * tanh_fast(acc[mi][ni][3] + add1);
        }
        sum0 += __shfl_xor_sync(0xffffffff, sum0, 1);
        sum0 += __shfl_xor_sync(0xffffffff, sum0, 2);
        sum1 += __shfl_xor_sync(0xffffffff, sum1, 1);
        sum1 += __shfl_xor_sync(0xffffffff, sum1, 2);
        if ((lane & 3) == 0) {
            int r = wm * 64 + mi * 16 + (lane >> 2);
            s_red[wn][r]     = sum0;
            s_red[wn][r + 8] = sum1;
        }
    }
    __syncthreads();
    if (tid < BM) {
        float part = (s_red[0][tid] + s_red[1][tid]) + (s_red[2][tid] + s_red[3][tid]);
        g_partial[(row0 + tid) * NTILES + ntile] = part;
    }
}

// ---------------------------------------------------------------------------
// 4) Softmax over L per batch; writes attention weights into d_out half 2
// ---------------------------------------------------------------------------
__global__ __launch_bounds__(256) void softmax_kernel(const float* __restrict__ bV,
                                                      float* __restrict__ out_w) {
    __shared__ float sl[LEN];
    __shared__ float sred[256];
    int b = blockIdx.x, tid = threadIdx.x;
    float bv = bV[0];
    float lmax = -1e30f;
    for (int i = tid; i < LEN; i += 256) {
        const float* p = g_partial + (size_t)(b * LEN + i) * NTILES;
        float s = (p[0] + p[1]) + (p[2] + p[3]) + bv;
        sl[i] = s;
        lmax = fmaxf(lmax, s);
    }
    sred[tid] = lmax;
    __syncthreads();
    for (int s = 128; s > 0; s >>= 1) {
        if (tid < s) sred[tid] = fmaxf(sred[tid], sred[tid + s]);
        __syncthreads();
    }
    float mx = sred[0];
    __syncthreads();
    float lsum = 0.f;
    for (int i = tid; i < LEN; i += 256) {
        float e = expf(sl[i] - mx);
        sl[i] = e;
        lsum += e;
    }
    sred[tid] = lsum;
    __syncthreads();
    for (int s = 128; s > 0; s >>= 1) {
        if (tid < s) sred[tid] += sred[tid + s];
        __syncthreads();
    }
    float inv = 1.0f / sred[0];
    for (int i = tid; i < LEN; i += 256)
        out_w[(size_t)b * LEN + i] = sl[i] * inv;
}

// ---------------------------------------------------------------------------
// 5) context[b][d] = sum_l w[b][l] * features[b][l][d]
// ---------------------------------------------------------------------------
__global__ __launch_bounds__(256) void context_kernel(const float* __restrict__ features,
                                                      const float* __restrict__ w,
                                                      float* __restrict__ out) {
    __shared__ float sw[LEN];
    int b = blockIdx.y, chunk = blockIdx.x, tid = threadIdx.x;
    for (int i = tid; i < LEN; i += 256) sw[i] = w[(size_t)b * LEN + i];
    __syncthreads();
    int d = chunk * 256 + tid;
    const float* f = features + (size_t)b * LEN * DIM + d;
    float a0 = 0.f, a1 = 0.f, a2 = 0.f, a3 = 0.f;
    for (int l = 0; l < LEN; l += 4) {
        a0 += sw[l]     * f[(size_t)l * DIM];
        a1 += sw[l + 1] * f[(size_t)(l + 1) * DIM];
        a2 += sw[l + 2] * f[(size_t)(l + 2) * DIM];
        a3 += sw[l + 3] * f[(size_t)(l + 3) * DIM];
    }
    out[(size_t)b * DIM + d] = (a0 + a1) + (a2 + a3);
}

// ---------------------------------------------------------------------------
extern "C" void kernel_launch(void* const* d_in, const int* in_sizes, int n_in,
                              void* d_out, int out_size) {
    const float* features = (const float*)d_in[0];
    const float* hidden   = (const float*)d_in[1];
    const float* W1       = (const float*)d_in[2];
    const float* b1       = (const float*)d_in[3];
    const float* W2       = (const float*)d_in[4];
    const float* b2       = (const float*)d_in[5];
    const float* V        = (const float*)d_in[6];
    const float* bV       = (const float*)d_in[7];

    float* out_ctx = (float*)d_out;                 // [B, D]
    float* out_w   = (float*)d_out + BATCH * DIM;   // [B, L, 1]

    static bool attr_set = false;
    if (!attr_set) {
        cudaFuncSetAttribute(fused_gemm_mma, cudaFuncAttributeMaxDynamicSharedMemorySize, DYN_SMEM);
        attr_set = true;
    }

    transpose_w1_kernel<<<dim3(32, 32), dim3(32, 8)>>>(W1);
    projh_kernel<<<UNITS / 64, 512>>>(hidden, W2, b2);
    fused_gemm_mma<<<dim3(NTILES, MROWS / BM), 256, DYN_SMEM>>>(features, b1, V);
    softmax_kernel<<<BATCH, 256>>>(bV, out_w);
    context_kernel<<<dim3(DIM / 256, BATCH), 256>>>(features, out_w, out_ctx);
}

// round 6
// speedup vs baseline: 1.5038x; 1.0148x over previous
#include <cuda_runtime.h>
#include <cuda_bf16.h>
#include <cstdint>
#include <math.h>

// Problem shape (fixed)
#define BATCH 64
#define LEN   1024
#define DIM   1024
#define HID   1024
#define UNITS 1024
#define MROWS (BATCH * LEN)   // 65536

// GEMM tiling (mma.sync tf32; tcgen05 unavailable — PTX targets compute_103)
#define BM 128
#define BN 256
#define BK 32                 // floats per k-chunk = 128 bytes/row
#define KT (DIM / BK)         // 32
#define NTILES (UNITS / BN)   // 4
#define STAGES 4
#define STAGE_A_BYTES (BM * 128)                       // 16384
#define STAGE_B_BYTES (BN * 128)                       // 32768
#define STAGE_BYTES   (STAGE_A_BYTES + STAGE_B_BYTES)  // 49152
#define DYN_SMEM (STAGES * STAGE_BYTES)                // 196608

// Scratch (__device__ globals; no allocation allowed)
__device__ float g_w1t[(size_t)UNITS * DIM];        // W1 transposed [u][d], tf32-rounded
__device__ float g_projh[BATCH * UNITS];            // hidden @ W2 + b2
__device__ float g_partial[(size_t)MROWS * NTILES]; // partial logits per (row, ntile)

// ---------------------------------------------------------------------------
// helpers
// ---------------------------------------------------------------------------
__device__ __forceinline__ uint32_t smem_u32(const void* p) {
    uint32_t a;
    asm("{ .reg .u64 t; cvta.to.shared.u64 t, %1; cvt.u32.u64 %0, t; }" : "=r"(a) : "l"(p));
    return a;
}

__device__ __forceinline__ uint32_t f2tf32(float x) {
    uint32_t r;
    asm("cvt.rna.tf32.f32 %0, %1;" : "=r"(r) : "f"(x));
    return r;
}

#define CP_ASYNC16(dst, src) \
    asm volatile("cp.async.cg.shared.global [%0], [%1], 16;" :: "r"(dst), "l"(src))
#define CP_COMMIT() asm volatile("cp.async.commit_group;" ::: "memory")
#define CP_WAIT2()  asm volatile("cp.async.wait_group 2;" ::: "memory")
#define CP_WAIT0()  asm volatile("cp.async.wait_group 0;" ::: "memory")

#define LDSM_X4(r, addr)                                                        \
    asm volatile("ldmatrix.sync.aligned.m8n8.x4.shared.b16 {%0,%1,%2,%3}, [%4];" \
                 : "=r"((r)[0]), "=r"((r)[1]), "=r"((r)[2]), "=r"((r)[3])        \
                 : "r"(addr))

__device__ __forceinline__ void mma_tf32(float c[4], const uint32_t a[4],
                                         uint32_t b0, uint32_t b1) {
    asm volatile(
        "mma.sync.aligned.m16n8k8.row.col.f32.tf32.tf32.f32 "
        "{%0,%1,%2,%3}, {%4,%5,%6,%7}, {%8,%9}, {%0,%1,%2,%3};\n"
        : "+f"(c[0]), "+f"(c[1]), "+f"(c[2]), "+f"(c[3])
        : "r"(a[0]), "r"(a[1]), "r"(a[2]), "r"(a[3]), "r"(b0), "r"(b1));
}

__device__ __forceinline__ float tanh_fast(float x) {
    float e = __expf(2.0f * x);
    return 1.0f - __fdividef(2.0f, e + 1.0f);
}

// ---------------------------------------------------------------------------
// 1) Transpose W1 [D][U] -> g_w1t [U][D], rounded to tf32 (rna)
// ---------------------------------------------------------------------------
__global__ void transpose_w1_kernel(const float* __restrict__ W1) {
    __shared__ float tile[32][33];
    int u = blockIdx.x * 32 + threadIdx.x;
    int d0 = blockIdx.y * 32;
#pragma unroll
    for (int j = 0; j < 32; j += 8)
        tile[threadIdx.y + j][threadIdx.x] = W1[(size_t)(d0 + threadIdx.y + j) * UNITS + u];
    __syncthreads();
    int dd = d0 + threadIdx.x;
    int u0 = blockIdx.x * 32;
#pragma unroll
    for (int j = 0; j < 32; j += 8)
        g_w1t[(size_t)(u0 + threadIdx.y + j) * DIM + dd] =
            __uint_as_float(f2tf32(tile[threadIdx.x][threadIdx.y + j]));
}

// ---------------------------------------------------------------------------
// 2) proj_h = hidden @ W2 + b2 — tiled so W2 is read exactly once
// ---------------------------------------------------------------------------
__global__ __launch_bounds__(512) void projh_kernel(const float* __restrict__ hidden,
                                                    const float* __restrict__ W2,
                                                    const float* __restrict__ b2) {
    __shared__ float sh[64][65];
    __shared__ float sw[64][65];
    const int tid = threadIdx.x;
    const int u0 = blockIdx.x * 64;
    const int uu = tid & 63;
    const int bb = (tid >> 6) * 8;
    float acc[8] = {0.f, 0.f, 0.f, 0.f, 0.f, 0.f, 0.f, 0.f};

    for (int hc = 0; hc < HID / 64; hc++) {
        const int h0 = hc * 64;
#pragma unroll
        for (int i = 0; i < 8; i++) {
            int idx = tid + i * 512;
            int b = idx >> 6, h = idx & 63;
            sh[b][h] = hidden[(size_t)b * HID + h0 + h];
        }
#pragma unroll
        for (int i = 0; i < 8; i++) {
            int idx = tid + i * 512;
            int h = idx >> 6, u = idx & 63;
            sw[h][u] = W2[(size_t)(h0 + h) * UNITS + u0 + u];
        }
        __syncthreads();
#pragma unroll 16
        for (int h = 0; h < 64; h++) {
            float w = sw[h][uu];
#pragma unroll
            for (int j = 0; j < 8; j++)
                acc[j] += sh[bb + j][h] * w;
        }
        __syncthreads();
    }
    float bias = b2[u0 + uu];
#pragma unroll
    for (int j = 0; j < 8; j++)
        g_projh[(size_t)(bb + j) * UNITS + u0 + uu] = acc[j] + bias;
}

// ---------------------------------------------------------------------------
// 3) Fused GEMM: cp.async 4-stage, single barrier/iter, ks-pipelined ldmatrix
//    grid (NTILES, MROWS/BM) = (4, 512); 256 threads = 8 warps (2m x 4n)
//    warp tile 64x64 (128 acc regs)
// ---------------------------------------------------------------------------
__global__ __launch_bounds__(256, 1) void fused_gemm_mma(const float* __restrict__ features,
                                                         const float* __restrict__ b1,
                                                         const float* __restrict__ V) {
    extern __shared__ char dsmem_raw[];
    __shared__ float s_red[4][BM];
    __shared__ float s_add[BN];
    __shared__ float s_v[BN];

    const int tid  = threadIdx.x;
    const int lane = tid & 31;
    const int warp = tid >> 5;          // 0..7
    const int wm   = warp >> 2;         // 0..1
    const int wn   = warp & 3;          // 0..3
    const int ntile = blockIdx.x;
    const int mtile = blockIdx.y;
    const size_t row0 = (size_t)mtile * BM;
    const int u0 = ntile * BN;
    const int b = mtile >> 3;           // LEN/BM = 8 m-tiles per batch

    const uint32_t smem0 = smem_u32(dsmem_raw);

    s_add[tid] = g_projh[(size_t)b * UNITS + u0 + tid] + b1[u0 + tid];
    s_v[tid]   = V[u0 + tid];

    float acc[4][8][4];
#pragma unroll
    for (int mi = 0; mi < 4; mi++)
#pragma unroll
        for (int ni = 0; ni < 8; ni++)
#pragma unroll
            for (int j = 0; j < 4; j++) acc[mi][ni][j] = 0.f;

    const float* Ag = features + row0 * DIM;
    const float* Bg = g_w1t + (size_t)u0 * DIM;

    // loader constants (256 threads, 8 threads/row, 16B each)
    const int lrow  = tid >> 3;                // 0..31
    const int lcolf = (tid & 7) * 4;
    const uint32_t lsw = ((uint32_t)(tid & 7) * 16) ^ ((uint32_t)(lrow & 7) << 4);

    // ldmatrix per-lane constants
    const uint32_t xorp  = (uint32_t)(lane & 7) << 4;
    const uint32_t aRowB = (uint32_t)(wm * 64 + ((lane >> 3) & 1) * 8 + (lane & 7)) * 128;
    const uint32_t aColB = (uint32_t)(lane >> 4) * 16;
    const uint32_t bRowB = (uint32_t)(wn * 64 + ((lane >> 4) & 1) * 8 + (lane & 7)) * 128;
    const uint32_t bColB = (uint32_t)((lane >> 3) & 1) * 16;

    auto load_stage = [&](int itL, int slot) {
        const uint32_t sA = smem0 + slot * STAGE_BYTES;
        const uint32_t sB = sA + STAGE_A_BYTES;
        const int k0 = itL * BK;
#pragma unroll
        for (int p = 0; p < 4; p++) {          // A: 128 rows
            int r = lrow + p * 32;
            CP_ASYNC16(sA + (uint32_t)r * 128 + lsw, Ag + (size_t)r * DIM + k0 + lcolf);
        }
#pragma unroll
        for (int p = 0; p < 8; p++) {          // B: 256 rows
            int r = lrow + p * 32;
            CP_ASYNC16(sB + (uint32_t)r * 128 + lsw, Bg + (size_t)r * DIM + k0 + lcolf);
        }
    };

    load_stage(0, 0); CP_COMMIT();
    load_stage(1, 1); CP_COMMIT();
    load_stage(2, 2); CP_COMMIT();

#pragma unroll 1
    for (int it = 0; it < KT; it++) {
        CP_WAIT2();          // stage `it` resident (outstanding <= 2 newest)
        __syncthreads();     // all warps done with stage it-1; loads landed chip-wide

        const int ls = it + STAGES - 1;
        if (ls < KT) load_stage(ls, ls & (STAGES - 1));
        CP_COMMIT();         // commit every iter to keep group counting uniform

        const uint32_t sA = smem0 + (it & (STAGES - 1)) * STAGE_BYTES;
        const uint32_t sB = sA + STAGE_A_BYTES;

        uint32_t afr[2][4][4], bfr[2][4][4];
        // prefetch ks = 0 fragments
        {
            const uint32_t ac = aColB ^ xorp;
            const uint32_t bc = bColB ^ xorp;
#pragma unroll
            for (int mi = 0; mi < 4; mi++)
                LDSM_X4(afr[0][mi], sA + aRowB + (uint32_t)mi * 2048 + ac);
#pragma unroll
            for (int p = 0; p < 4; p++)
                LDSM_X4(bfr[0][p], sB + bRowB + (uint32_t)p * 2048 + bc);
        }
#pragma unroll
        for (int ks = 0; ks < 4; ks++) {
            const int cur = ks & 1, nxt = cur ^ 1;
            if (ks < 3) {
                const uint32_t ac = ((uint32_t)((ks + 1) * 32) + aColB) ^ xorp;
                const uint32_t bc = ((uint32_t)((ks + 1) * 32) + bColB) ^ xorp;
#pragma unroll
                for (int mi = 0; mi < 4; mi++)
                    LDSM_X4(afr[nxt][mi], sA + aRowB + (uint32_t)mi * 2048 + ac);
#pragma unroll
                for (int p = 0; p < 4; p++)
                    LDSM_X4(bfr[nxt][p], sB + bRowB + (uint32_t)p * 2048 + bc);
            }
#pragma unroll
            for (int mi = 0; mi < 4; mi++) {
#pragma unroll
                for (int p = 0; p < 4; p++) {
                    mma_tf32(acc[mi][2 * p],     afr[cur][mi], bfr[cur][p][0], bfr[cur][p][1]);
                    mma_tf32(acc[mi][2 * p + 1], afr[cur][mi], bfr[cur][p][2], bfr[cur][p][3]);
                }
            }
        }
    }
    CP_WAIT0();

    // ---- epilogue: tanh(acc + proj_h + b1) . V, reduce over BN ----
#pragma unroll
    for (int mi = 0; mi < 4; mi++) {
        float sum0 = 0.f, sum1 = 0.f;
#pragma unroll
        for (int ni = 0; ni < 8; ni++) {
            int c = wn * 64 + ni * 8 + 2 * (lane & 3);
            float add0 = s_add[c], add1 = s_add[c + 1];
            float v0 = s_v[c], v1 = s_v[c + 1];
            sum0 += v0 * tanh_fast(acc[mi][ni][0] + add0) + v1 * tanh_fast(acc[mi][ni][1] + add1);
            sum1 += v0 * tanh_fast(acc[mi][ni][2] + add0) + v1 * tanh_fast(acc[mi][ni][3] + add1);
        }
        sum0 += __shfl_xor_sync(0xffffffff, sum0, 1);
        sum0 += __shfl_xor_sync(0xffffffff, sum0, 2);
        sum1 += __shfl_xor_sync(0xffffffff, sum1, 1);
        sum1 += __shfl_xor_sync(0xffffffff, sum1, 2);
        if ((lane & 3) == 0) {
            int r = wm * 64 + mi * 16 + (lane >> 2);
            s_red[wn][r]     = sum0;
            s_red[wn][r + 8] = sum1;
        }
    }
    __syncthreads();
    if (tid < BM) {
        float part = (s_red[0][tid] + s_red[1][tid]) + (s_red[2][tid] + s_red[3][tid]);
        g_partial[(row0 + tid) * NTILES + ntile] = part;
    }
}

// ---------------------------------------------------------------------------
// 4) Softmax over L per batch
// ---------------------------------------------------------------------------
__global__ __launch_bounds__(256) void softmax_kernel(const float* __restrict__ bV,
                                                      float* __restrict__ out_w) {
    __shared__ float sl[LEN];
    __shared__ float sred[256];
    int b = blockIdx.x, tid = threadIdx.x;
    float bv = bV[0];
    float lmax = -1e30f;
    for (int i = tid; i < LEN; i += 256) {
        const float* p = g_partial + (size_t)(b * LEN + i) * NTILES;
        float s = (p[0] + p[1]) + (p[2] + p[3]) + bv;
        sl[i] = s;
        lmax = fmaxf(lmax, s);
    }
    sred[tid] = lmax;
    __syncthreads();
    for (int s = 128; s > 0; s >>= 1) {
        if (tid < s) sred[tid] = fmaxf(sred[tid], sred[tid + s]);
        __syncthreads();
    }
    float mx = sred[0];
    __syncthreads();
    float lsum = 0.f;
    for (int i = tid; i < LEN; i += 256) {
        float e = expf(sl[i] - mx);
        sl[i] = e;
        lsum += e;
    }
    sred[tid] = lsum;
    __syncthreads();
    for (int s = 128; s > 0; s >>= 1) {
        if (tid < s) sred[tid] += sred[tid + s];
        __syncthreads();
    }
    float inv = 1.0f / sred[0];
    for (int i = tid; i < LEN; i += 256)
        out_w[(size_t)b * LEN + i] = sl[i] * inv;
}

// ---------------------------------------------------------------------------
// 5) context[b][d] = sum_l w[b][l] * features[b][l][d]
// ---------------------------------------------------------------------------
__global__ __launch_bounds__(256) void context_kernel(const float* __restrict__ features,
                                                      const float* __restrict__ w,
                                                      float* __restrict__ out) {
    __shared__ float sw[LEN];
    int b = blockIdx.y, chunk = blockIdx.x, tid = threadIdx.x;
    for (int i = tid; i < LEN; i += 256) sw[i] = w[(size_t)b * LEN + i];
    __syncthreads();
    int d = chunk * 256 + tid;
    const float* f = features + (size_t)b * LEN * DIM + d;
    float a0 = 0.f, a1 = 0.f, a2 = 0.f, a3 = 0.f;
    for (int l = 0; l < LEN; l += 4) {
        a0 += sw[l]     * f[(size_t)l * DIM];
        a1 += sw[l + 1] * f[(size_t)(l + 1) * DIM];
        a2 += sw[l + 2] * f[(size_t)(l + 2) * DIM];
        a3 += sw[l + 3] * f[(size_t)(l + 3) * DIM];
    }
    out[(size_t)b * DIM + d] = (a0 + a1) + (a2 + a3);
}

// ---------------------------------------------------------------------------
extern "C" void kernel_launch(void* const* d_in, const int* in_sizes, int n_in,
                              void* d_out, int out_size) {
    const float* features = (const float*)d_in[0];
    const float* hidden   = (const float*)d_in[1];
    const float* W1       = (const float*)d_in[2];
    const float* b1       = (const float*)d_in[3];
    const float* W2       = (const float*)d_in[4];
    const float* b2       = (const float*)d_in[5];
    const float* V        = (const float*)d_in[6];
    const float* bV       = (const float*)d_in[7];

    float* out_ctx = (float*)d_out;                 // [B, D]
    float* out_w   = (float*)d_out + BATCH * DIM;   // [B, L, 1]

    static bool attr_set = false;
    if (!attr_set) {
        cudaFuncSetAttribute(fused_gemm_mma, cudaFuncAttributeMaxDynamicSharedMemorySize, DYN_SMEM);
        attr_set = true;
    }

    transpose_w1_kernel<<<dim3(32, 32), dim3(32, 8)>>>(W1);
    projh_kernel<<<UNITS / 64, 512>>>(hidden, W2, b2);
    fused_gemm_mma<<<dim3(NTILES, MROWS / BM), 256, DYN_SMEM>>>(features, b1, V);
    softmax_kernel<<<BATCH, 256>>>(bV, out_w);
    context_kernel<<<dim3(DIM / 256, BATCH), 256>>>(features, out_w, out_ctx);
}

// round 9
// speedup vs baseline: 1.5157x; 1.0079x over previous
#include <cuda_runtime.h>
#include <cuda_bf16.h>
#include <cstdint>
#include <math.h>

// Problem shape (fixed)
#define BATCH 64
#define LEN   1024
#define DIM   1024
#define HID   1024
#define UNITS 1024
#define MROWS (BATCH * LEN)   // 65536

// GEMM tiling (mma.sync tf32; tcgen05 unavailable — PTX targets compute_103)
#define BM 128
#define BN 256
#define BK 32                 // floats per k-chunk = 128 bytes/row
#define KT (DIM / BK)         // 32
#define NTILES (UNITS / BN)   // 4
#define STAGES 4
#define STAGE_A_BYTES (BM * 128)                       // 16384
#define STAGE_B_BYTES (BN * 128)                       // 32768
#define STAGE_BYTES   (STAGE_A_BYTES + STAGE_B_BYTES)  // 49152
#define DYN_SMEM (STAGES * STAGE_BYTES)                // 196608

// Scratch (__device__ globals; no allocation allowed)
__device__ float g_w1t[(size_t)UNITS * DIM];        // W1 transposed [u][d], tf32-rounded
__device__ float g_projh[BATCH * UNITS];            // hidden @ W2 + b2
__device__ float g_partial[(size_t)MROWS * NTILES]; // partial logits per (row, ntile)

// ---------------------------------------------------------------------------
// helpers
// ---------------------------------------------------------------------------
__device__ __forceinline__ uint32_t smem_u32(const void* p) {
    uint32_t a;
    asm("{ .reg .u64 t; cvta.to.shared.u64 t, %1; cvt.u32.u64 %0, t; }" : "=r"(a) : "l"(p));
    return a;
}

__device__ __forceinline__ uint32_t f2tf32(float x) {
    uint32_t r;
    asm("cvt.rna.tf32.f32 %0, %1;" : "=r"(r) : "f"(x));
    return r;
}

#define CP_ASYNC16(dst, src) \
    asm volatile("cp.async.cg.shared.global [%0], [%1], 16;" :: "r"(dst), "l"(src))
#define CP_COMMIT() asm volatile("cp.async.commit_group;" ::: "memory")
#define CP_WAIT2()  asm volatile("cp.async.wait_group 2;" ::: "memory")
#define CP_WAIT0()  asm volatile("cp.async.wait_group 0;" ::: "memory")

#define LDSM_X4(r, addr)                                                        \
    asm volatile("ldmatrix.sync.aligned.m8n8.x4.shared.b16 {%0,%1,%2,%3}, [%4];" \
                 : "=r"((r)[0]), "=r"((r)[1]), "=r"((r)[2]), "=r"((r)[3])        \
                 : "r"(addr))

__device__ __forceinline__ void mma_tf32(float c[4], const uint32_t a[4],
                                         uint32_t b0, uint32_t b1) {
    asm volatile(
        "mma.sync.aligned.m16n8k8.row.col.f32.tf32.tf32.f32 "
        "{%0,%1,%2,%3}, {%4,%5,%6,%7}, {%8,%9}, {%0,%1,%2,%3};\n"
        : "+f"(c[0]), "+f"(c[1]), "+f"(c[2]), "+f"(c[3])
        : "r"(a[0]), "r"(a[1]), "r"(a[2]), "r"(a[3]), "r"(b0), "r"(b1));
}

__device__ __forceinline__ float tanh_fast(float x) {
    float e = __expf(2.0f * x);
    return 1.0f - __fdividef(2.0f, e + 1.0f);
}

// ---------------------------------------------------------------------------
// 1) Transpose W1 [D][U] -> g_w1t [U][D], rounded to tf32 (rna)
// ---------------------------------------------------------------------------
__global__ void transpose_w1_kernel(const float* __restrict__ W1) {
    __shared__ float tile[32][33];
    int u = blockIdx.x * 32 + threadIdx.x;
    int d0 = blockIdx.y * 32;
#pragma unroll
    for (int j = 0; j < 32; j += 8)
        tile[threadIdx.y + j][threadIdx.x] = W1[(size_t)(d0 + threadIdx.y + j) * UNITS + u];
    __syncthreads();
    int dd = d0 + threadIdx.x;
    int u0 = blockIdx.x * 32;
#pragma unroll
    for (int j = 0; j < 32; j += 8)
        g_w1t[(size_t)(u0 + threadIdx.y + j) * DIM + dd] =
            __uint_as_float(f2tf32(tile[threadIdx.x][threadIdx.y + j]));
}

// ---------------------------------------------------------------------------
// 2) proj_h = hidden @ W2 + b2 — tiled so W2 is read exactly once
// ---------------------------------------------------------------------------
__global__ __launch_bounds__(512) void projh_kernel(const float* __restrict__ hidden,
                                                    const float* __restrict__ W2,
                                                    const float* __restrict__ b2) {
    __shared__ float sh[64][65];
    __shared__ float sw[64][65];
    const int tid = threadIdx.x;
    const int u0 = blockIdx.x * 64;
    const int uu = tid & 63;
    const int bb = (tid >> 6) * 8;
    float acc[8] = {0.f, 0.f, 0.f, 0.f, 0.f, 0.f, 0.f, 0.f};

    for (int hc = 0; hc < HID / 64; hc++) {
        const int h0 = hc * 64;
#pragma unroll
        for (int i = 0; i < 8; i++) {
            int idx = tid + i * 512;
            int b = idx >> 6, h = idx & 63;
            sh[b][h] = hidden[(size_t)b * HID + h0 + h];
        }
#pragma unroll
        for (int i = 0; i < 8; i++) {
            int idx = tid + i * 512;
            int h = idx >> 6, u = idx & 63;
            sw[h][u] = W2[(size_t)(h0 + h) * UNITS + u0 + u];
        }
        __syncthreads();
#pragma unroll 16
        for (int h = 0; h < 64; h++) {
            float w = sw[h][uu];
#pragma unroll
            for (int j = 0; j < 8; j++)
                acc[j] += sh[bb + j][h] * w;
        }
        __syncthreads();
    }
    float bias = b2[u0 + uu];
#pragma unroll
    for (int j = 0; j < 8; j++)
        g_projh[(size_t)(bb + j) * UNITS + u0 + uu] = acc[j] + bias;
}

// ---------------------------------------------------------------------------
// 3) Fused GEMM: cp.async 4-stage, single barrier/iter
//    grid (NTILES, MROWS/BM) = (4, 512); 512 threads = 16 warps (2m x 8n)
//    warp tile 64x32 -> 4 warps/SMSP for LDS<->MMA overlap
// ---------------------------------------------------------------------------
__global__ __launch_bounds__(512, 1) void fused_gemm_mma(const float* __restrict__ features,
                                                         const float* __restrict__ b1,
                                                         const float* __restrict__ V) {
    extern __shared__ char dsmem_raw[];
    __shared__ float s_red[8][BM];
    __shared__ float s_add[BN];
    __shared__ float s_v[BN];

    const int tid  = threadIdx.x;
    const int lane = tid & 31;
    const int warp = tid >> 5;          // 0..15
    const int wm   = warp >> 3;         // 0..1
    const int wn   = warp & 7;          // 0..7
    const int ntile = blockIdx.x;
    const int mtile = blockIdx.y;
    const size_t row0 = (size_t)mtile * BM;
    const int u0 = ntile * BN;
    const int b = mtile >> 3;           // LEN/BM = 8 m-tiles per batch

    const uint32_t smem0 = smem_u32(dsmem_raw);

    if (tid < BN) {
        s_add[tid] = g_projh[(size_t)b * UNITS + u0 + tid] + b1[u0 + tid];
        s_v[tid]   = V[u0 + tid];
    }

    float acc[4][4][4];
#pragma unroll
    for (int mi = 0; mi < 4; mi++)
#pragma unroll
        for (int ni = 0; ni < 4; ni++)
#pragma unroll
            for (int j = 0; j < 4; j++) acc[mi][ni][j] = 0.f;

    const float* Ag = features + row0 * DIM;
    const float* Bg = g_w1t + (size_t)u0 * DIM;

    // loader constants (512 threads, 8 threads/row, 16B each)
    const int lrow  = tid >> 3;                // 0..63
    const int lcolf = (tid & 7) * 4;
    const uint32_t lsw = ((uint32_t)(tid & 7) * 16) ^ ((uint32_t)(lrow & 7) << 4);

    // ldmatrix per-lane constants
    const uint32_t xorp  = (uint32_t)(lane & 7) << 4;
    const uint32_t aRowB = (uint32_t)(wm * 64 + ((lane >> 3) & 1) * 8 + (lane & 7)) * 128;
    const uint32_t aColB = (uint32_t)(lane >> 4) * 16;
    const uint32_t bRowB = (uint32_t)(wn * 32 + ((lane >> 4) & 1) * 8 + (lane & 7)) * 128;
    const uint32_t bColB = (uint32_t)((lane >> 3) & 1) * 16;

    auto load_stage = [&](int itL, int slot) {
        const uint32_t sA = smem0 + slot * STAGE_BYTES;
        const uint32_t sB = sA + STAGE_A_BYTES;
        const int k0 = itL * BK;
#pragma unroll
        for (int p = 0; p < 2; p++) {          // A: 128 rows
            int r = lrow + p * 64;
            CP_ASYNC16(sA + (uint32_t)r * 128 + lsw, Ag + (size_t)r * DIM + k0 + lcolf);
        }
#pragma unroll
        for (int p = 0; p < 4; p++) {          // B: 256 rows
            int r = lrow + p * 64;
            CP_ASYNC16(sB + (uint32_t)r * 128 + lsw, Bg + (size_t)r * DIM + k0 + lcolf);
        }
    };

    load_stage(0, 0); CP_COMMIT();
    load_stage(1, 1); CP_COMMIT();
    load_stage(2, 2); CP_COMMIT();

#pragma unroll 1
    for (int it = 0; it < KT; it++) {
        CP_WAIT2();          // stage `it` resident
        __syncthreads();

        const int ls = it + STAGES - 1;
        if (ls < KT) load_stage(ls, ls & (STAGES - 1));
        CP_COMMIT();         // uniform group counting

        const uint32_t sA = smem0 + (it & (STAGES - 1)) * STAGE_BYTES;
        const uint32_t sB = sA + STAGE_A_BYTES;
#pragma unroll
        for (int ks = 0; ks < 4; ks++) {
            const uint32_t ac = ((uint32_t)(ks * 32) + aColB) ^ xorp;
            const uint32_t bc = ((uint32_t)(ks * 32) + bColB) ^ xorp;
            uint32_t afr[4][4];
#pragma unroll
            for (int mi = 0; mi < 4; mi++)
                LDSM_X4(afr[mi], sA + aRowB + (uint32_t)mi * 2048 + ac);
            uint32_t bfr[2][4];
#pragma unroll
            for (int p = 0; p < 2; p++)
                LDSM_X4(bfr[p], sB + bRowB + (uint32_t)p * 2048 + bc);
#pragma unroll
            for (int mi = 0; mi < 4; mi++) {
#pragma unroll
                for (int p = 0; p < 2; p++) {
                    mma_tf32(acc[mi][2 * p],     afr[mi], bfr[p][0], bfr[p][1]);
                    mma_tf32(acc[mi][2 * p + 1], afr[mi], bfr[p][2], bfr[p][3]);
                }
            }
        }
    }
    CP_WAIT0();

    // ---- epilogue: tanh(acc + proj_h + b1) . V, reduce over BN ----
#pragma unroll
    for (int mi = 0; mi < 4; mi++) {
        float sum0 = 0.f, sum1 = 0.f;
#pragma unroll
        for (int ni = 0; ni < 4; ni++) {
            int c = wn * 32 + ni * 8 + 2 * (lane & 3);
            float add0 = s_add[c], add1 = s_add[c + 1];
            float v0 = s_v[c], v1 = s_v[c + 1];
            sum0 += v0 * tanh_fast(acc[mi][ni][0] + add0) + v1 * tanh_fast(acc[mi][ni][1] + add1);
            sum1 += v0 * tanh_fast(acc[mi][ni][2] + add0) + v1 * tanh_fast(acc[mi][ni][3] + add1);
        }
        sum0 += __shfl_xor_sync(0xffffffff, sum0, 1);
        sum0 += __shfl_xor_sync(0xffffffff, sum0, 2);
        sum1 += __shfl_xor_sync(0xffffffff, sum1, 1);
        sum1 += __shfl_xor_sync(0xffffffff, sum1, 2);
        if ((lane & 3) == 0) {
            int r = wm * 64 + mi * 16 + (lane >> 2);
            s_red[wn][r]     = sum0;
            s_red[wn][r + 8] = sum1;
        }
    }
    __syncthreads();
    if (tid < BM) {
        float part = ((s_red[0][tid] + s_red[1][tid]) + (s_red[2][tid] + s_red[3][tid])) +
                     ((s_red[4][tid] + s_red[5][tid]) + (s_red[6][tid] + s_red[7][tid]));
        g_partial[(row0 + tid) * NTILES + ntile] = part;
    }
}

// ---------------------------------------------------------------------------
// 4) Softmax over L per batch
// ---------------------------------------------------------------------------
__global__ __launch_bounds__(256) void softmax_kernel(const float* __restrict__ bV,
                                                      float* __restrict__ out_w) {
    __shared__ float sl[LEN];
    __shared__ float sred[256];
    int b = blockIdx.x, tid = threadIdx.x;
    float bv = bV[0];
    float lmax = -1e30f;
    for (int i = tid; i < LEN; i += 256) {
        const float* p = g_partial + (size_t)(b * LEN + i) * NTILES;
        float s = (p[0] + p[1]) + (p[2] + p[3]) + bv;
        sl[i] = s;
        lmax = fmaxf(lmax, s);
    }
    sred[tid] = lmax;
    __syncthreads();
    for (int s = 128; s > 0; s >>= 1) {
        if (tid < s) sred[tid] = fmaxf(sred[tid], sred[tid + s]);
        __syncthreads();
    }
    float mx = sred[0];
    __syncthreads();
    float lsum = 0.f;
    for (int i = tid; i < LEN; i += 256) {
        float e = expf(sl[i] - mx);
        sl[i] = e;
        lsum += e;
    }
    sred[tid] = lsum;
    __syncthreads();
    for (int s = 128; s > 0; s >>= 1) {
        if (tid < s) sred[tid] += sred[tid + s];
        __syncthreads();
    }
    float inv = 1.0f / sred[0];
    for (int i = tid; i < LEN; i += 256)
        out_w[(size_t)b * LEN + i] = sl[i] * inv;
}

// ---------------------------------------------------------------------------
// 5) context[b][d] = sum_l w[b][l] * features[b][l][d]
// ---------------------------------------------------------------------------
__global__ __launch_bounds__(256) void context_kernel(const float* __restrict__ features,
                                                      const float* __restrict__ w,
                                                      float* __restrict__ out) {
    __shared__ float sw[LEN];
    int b = blockIdx.y, chunk = blockIdx.x, tid = threadIdx.x;
    for (int i = tid; i < LEN; i += 256) sw[i] = w[(size_t)b * LEN + i];
    __syncthreads();
    int d = chunk * 256 + tid;
    const float* f = features + (size_t)b * LEN * DIM + d;
    float a0 = 0.f, a1 = 0.f, a2 = 0.f, a3 = 0.f;
    for (int l = 0; l < LEN; l += 4) {
        a0 += sw[l]     * f[(size_t)l * DIM];
        a1 += sw[l + 1] * f[(size_t)(l + 1) * DIM];
        a2 += sw[l + 2] * f[(size_t)(l + 2) * DIM];
        a3 += sw[l + 3] * f[(size_t)(l + 3) * DIM];
    }
    out[(size_t)b * DIM + d] = (a0 + a1) + (a2 + a3);
}

// ---------------------------------------------------------------------------
extern "C" void kernel_launch(void* const* d_in, const int* in_sizes, int n_in,
                              void* d_out, int out_size) {
    const float* features = (const float*)d_in[0];
    const float* hidden   = (const float*)d_in[1];
    const float* W1       = (const float*)d_in[2];
    const float* b1       = (const float*)d_in[3];
    const float* W2       = (const float*)d_in[4];
    const float* b2       = (const float*)d_in[5];
    const float* V        = (const float*)d_in[6];
    const float* bV       = (const float*)d_in[7];

    float* out_ctx = (float*)d_out;                 // [B, D]
    float* out_w   = (float*)d_out + BATCH * DIM;   // [B, L, 1]

    static bool attr_set = false;
    if (!attr_set) {
        cudaFuncSetAttribute(fused_gemm_mma, cudaFuncAttributeMaxDynamicSharedMemorySize, DYN_SMEM);
        attr_set = true;
    }

    transpose_w1_kernel<<<dim3(32, 32), dim3(32, 8)>>>(W1);
    projh_kernel<<<UNITS / 64, 512>>>(hidden, W2, b2);
    fused_gemm_mma<<<dim3(NTILES, MROWS / BM), 512, DYN_SMEM>>>(features, b1, V);
    softmax_kernel<<<BATCH, 256>>>(bV, out_w);
    context_kernel<<<dim3(DIM / 256, BATCH), 256>>>(features, out_w, out_ctx);
}

// round 12
// speedup vs baseline: 2.1816x; 1.4394x over previous
#include <cuda_runtime.h>
#include <cuda_fp16.h>
#include <cstdint>
#include <math.h>

// Problem shape (fixed)
#define BATCH 64
#define LEN   1024
#define DIM   1024
#define HID   1024
#define UNITS 1024
#define MROWS (BATCH * LEN)   // 65536

// fp16 GEMM tiling (mma.sync m16n8k16 f16; tcgen05 unavailable on compute_103)
#define BM 128
#define BN 256
#define BKH 64                // halves per k-chunk = 128 bytes/row
#define KT (DIM / BKH)        // 16
#define NTILES (UNITS / BN)   // 4
#define STAGES 4
#define STAGE_A_BYTES (BM * 128)                       // 16384
#define STAGE_B_BYTES (BN * 128)                       // 32768
#define STAGE_BYTES   (STAGE_A_BYTES + STAGE_B_BYTES)  // 49152
#define DYN_SMEM (STAGES * STAGE_BYTES)                // 196608

// Scratch (__device__ globals; no allocation allowed)
__device__ __half g_feat_h[(size_t)MROWS * DIM];    // features in fp16 (128 MB)
__device__ __half g_w1t_h[(size_t)UNITS * DIM];     // W1 transposed [u][d], fp16 (2 MB, L2-resident)
__device__ float  g_projh[BATCH * UNITS];           // hidden @ W2 + b2
__device__ float  g_partial[(size_t)MROWS * NTILES];// partial logits per (row, ntile)

// ---------------------------------------------------------------------------
// helpers
// ---------------------------------------------------------------------------
__device__ __forceinline__ uint32_t smem_u32(const void* p) {
    uint32_t a;
    asm("{ .reg .u64 t; cvta.to.shared.u64 t, %1; cvt.u32.u64 %0, t; }" : "=r"(a) : "l"(p));
    return a;
}

__device__ __forceinline__ uint32_t h2_as_u32(__half2 h) {
    return *reinterpret_cast<uint32_t*>(&h);
}

#define CP_ASYNC16(dst, src) \
    asm volatile("cp.async.cg.shared.global [%0], [%1], 16;" :: "r"(dst), "l"(src))
#define CP_COMMIT() asm volatile("cp.async.commit_group;" ::: "memory")
#define CP_WAIT2()  asm volatile("cp.async.wait_group 2;" ::: "memory")
#define CP_WAIT0()  asm volatile("cp.async.wait_group 0;" ::: "memory")

#define LDSM_X4(r, addr)                                                        \
    asm volatile("ldmatrix.sync.aligned.m8n8.x4.shared.b16 {%0,%1,%2,%3}, [%4];" \
                 : "=r"((r)[0]), "=r"((r)[1]), "=r"((r)[2]), "=r"((r)[3])        \
                 : "r"(addr))

__device__ __forceinline__ void mma_f16(float c[4], const uint32_t a[4],
                                        uint32_t b0, uint32_t b1) {
    asm volatile(
        "mma.sync.aligned.m16n8k16.row.col.f32.f16.f16.f32 "
        "{%0,%1,%2,%3}, {%4,%5,%6,%7}, {%8,%9}, {%0,%1,%2,%3};\n"
        : "+f"(c[0]), "+f"(c[1]), "+f"(c[2]), "+f"(c[3])
        : "r"(a[0]), "r"(a[1]), "r"(a[2]), "r"(a[3]), "r"(b0), "r"(b1));
}

__device__ __forceinline__ float tanh_fast(float x) {
    float e = __expf(2.0f * x);
    return 1.0f - __fdividef(2.0f, e + 1.0f);
}

// ---------------------------------------------------------------------------
// 0) Convert features fp32 -> fp16 (rn). 8 floats per thread.
// ---------------------------------------------------------------------------
__global__ __launch_bounds__(256) void conv_feat_kernel(const float* __restrict__ features) {
    size_t i = ((size_t)blockIdx.x * 256 + threadIdx.x) * 8;
    float4 v0 = *(const float4*)(features + i);
    float4 v1 = *(const float4*)(features + i + 4);
    uint4 out;
    out.x = h2_as_u32(__floats2half2_rn(v0.x, v0.y));
    out.y = h2_as_u32(__floats2half2_rn(v0.z, v0.w));
    out.z = h2_as_u32(__floats2half2_rn(v1.x, v1.y));
    out.w = h2_as_u32(__floats2half2_rn(v1.z, v1.w));
    *(uint4*)(g_feat_h + i) = out;
}

// ---------------------------------------------------------------------------
// 1) Transpose W1 [D][U] -> g_w1t_h [U][D], fp16 (rn)
// ---------------------------------------------------------------------------
__global__ void prep_w1_kernel(const float* __restrict__ W1) {
    __shared__ float tile[32][33];
    int u = blockIdx.x * 32 + threadIdx.x;
    int d0 = blockIdx.y * 32;
#pragma unroll
    for (int j = 0; j < 32; j += 8)
        tile[threadIdx.y + j][threadIdx.x] = W1[(size_t)(d0 + threadIdx.y + j) * UNITS + u];
    __syncthreads();
    int dd = d0 + threadIdx.x;
    int u0 = blockIdx.x * 32;
#pragma unroll
    for (int j = 0; j < 32; j += 8)
        g_w1t_h[(size_t)(u0 + threadIdx.y + j) * DIM + dd] =
            __float2half_rn(tile[threadIdx.x][threadIdx.y + j]);
}

// ---------------------------------------------------------------------------
// 2) proj_h = hidden @ W2 + b2 — tiled so W2 is read exactly once (fp32 exact)
// ---------------------------------------------------------------------------
__global__ __launch_bounds__(512) void projh_kernel(const float* __restrict__ hidden,
                                                    const float* __restrict__ W2,
                                                    const float* __restrict__ b2) {
    __shared__ float sh[64][65];
    __shared__ float sw[64][65];
    const int tid = threadIdx.x;
    const int u0 = blockIdx.x * 64;
    const int uu = tid & 63;
    const int bb = (tid >> 6) * 8;
    float acc[8] = {0.f, 0.f, 0.f, 0.f, 0.f, 0.f, 0.f, 0.f};

    for (int hc = 0; hc < HID / 64; hc++) {
        const int h0 = hc * 64;
#pragma unroll
        for (int i = 0; i < 8; i++) {
            int idx = tid + i * 512;
            int b = idx >> 6, h = idx & 63;
            sh[b][h] = hidden[(size_t)b * HID + h0 + h];
        }
#pragma unroll
        for (int i = 0; i < 8; i++) {
            int idx = tid + i * 512;
            int h = idx >> 6, u = idx & 63;
            sw[h][u] = W2[(size_t)(h0 + h) * UNITS + u0 + u];
        }
        __syncthreads();
#pragma unroll 16
        for (int h = 0; h < 64; h++) {
            float w = sw[h][uu];
#pragma unroll
            for (int j = 0; j < 8; j++)
                acc[j] += sh[bb + j][h] * w;
        }
        __syncthreads();
    }
    float bias = b2[u0 + uu];
#pragma unroll
    for (int j = 0; j < 8; j++)
        g_projh[(size_t)(bb + j) * UNITS + u0 + uu] = acc[j] + bias;
}

// ---------------------------------------------------------------------------
// 3) Fused fp16 GEMM: cp.async 4-stage, single barrier/iter
//    grid (NTILES, MROWS/BM) = (4, 512); 512 threads = 16 warps (2m x 8n)
//    warp tile 64x32, mma m16n8k16 -> half the MMA instructions of tf32
// ---------------------------------------------------------------------------
__global__ __launch_bounds__(512, 1) void fused_gemm_f16(const float* __restrict__ b1,
                                                         const float* __restrict__ V) {
    extern __shared__ char dsmem_raw[];
    __shared__ float s_red[8][BM];
    __shared__ float s_add[BN];
    __shared__ float s_v[BN];

    const int tid  = threadIdx.x;
    const int lane = tid & 31;
    const int warp = tid >> 5;          // 0..15
    const int wm   = warp >> 3;         // 0..1
    const int wn   = warp & 7;          // 0..7
    const int ntile = blockIdx.x;
    const int mtile = blockIdx.y;
    const size_t row0 = (size_t)mtile * BM;
    const int u0 = ntile * BN;
    const int b = mtile >> 3;           // LEN/BM = 8 m-tiles per batch

    const uint32_t smem0 = smem_u32(dsmem_raw);

    if (tid < BN) {
        s_add[tid] = g_projh[(size_t)b * UNITS + u0 + tid] + b1[u0 + tid];
        s_v[tid]   = V[u0 + tid];
    }

    float acc[4][4][4];
#pragma unroll
    for (int mi = 0; mi < 4; mi++)
#pragma unroll
        for (int ni = 0; ni < 4; ni++)
#pragma unroll
            for (int j = 0; j < 4; j++) acc[mi][ni][j] = 0.f;

    const __half* Ag = g_feat_h + row0 * DIM;
    const __half* Bg = g_w1t_h + (size_t)u0 * DIM;

    // loader constants (512 threads, 8 threads/row of 128B, 16B each)
    const int lrow  = tid >> 3;                // 0..63
    const int lcolh = (tid & 7) * 8;           // half-index within row
    const uint32_t lsw = ((uint32_t)(tid & 7) * 16) ^ ((uint32_t)(lrow & 7) << 4);

    // ldmatrix per-lane constants (b16 fragments, 128B rows)
    // A x4: mat0 (m0..7,k0) mat1 (m8..15,k0) mat2 (m0..7,k8) mat3 (m8..15,k8)
    const uint32_t aRow  = (uint32_t)(wm * 64 + (lane & 7) + ((lane >> 3) & 1) * 8);
    const uint32_t aColB = (uint32_t)(lane >> 4) * 16;
    // B x4: mat0 (n0..7,k0) mat1 (n0..7,k8) mat2 (n8..15,k0) mat3 (n8..15,k8)
    const uint32_t bRow  = (uint32_t)(wn * 32 + (lane & 7) + (lane >> 4) * 8);
    const uint32_t bColB = (uint32_t)((lane >> 3) & 1) * 16;

    auto load_stage = [&](int itL, int slot) {
        const uint32_t sA = smem0 + slot * STAGE_BYTES;
        const uint32_t sB = sA + STAGE_A_BYTES;
        const int k0 = itL * BKH;
#pragma unroll
        for (int p = 0; p < 2; p++) {          // A: 128 rows
            int r = lrow + p * 64;
            CP_ASYNC16(sA + (uint32_t)r * 128 + lsw, Ag + (size_t)r * DIM + k0 + lcolh);
        }
#pragma unroll
        for (int p = 0; p < 4; p++) {          // B: 256 rows
            int r = lrow + p * 64;
            CP_ASYNC16(sB + (uint32_t)r * 128 + lsw, Bg + (size_t)r * DIM + k0 + lcolh);
        }
    };

    load_stage(0, 0); CP_COMMIT();
    load_stage(1, 1); CP_COMMIT();
    load_stage(2, 2); CP_COMMIT();

#pragma unroll 1
    for (int it = 0; it < KT; it++) {
        CP_WAIT2();          // stage `it` resident
        __syncthreads();

        const int ls = it + STAGES - 1;
        if (ls < KT) load_stage(ls, ls & (STAGES - 1));
        CP_COMMIT();         // uniform group counting

        const uint32_t sA = smem0 + (it & (STAGES - 1)) * STAGE_BYTES;
        const uint32_t sB = sA + STAGE_A_BYTES;
#pragma unroll
        for (int ks = 0; ks < 4; ks++) {       // k16 per step, 64 per chunk
            const uint32_t kb = (uint32_t)(ks * 32);  // byte offset of k-step
            uint32_t afr[4][4];
#pragma unroll
            for (int mi = 0; mi < 4; mi++) {
                uint32_t r = aRow + (uint32_t)mi * 16;
                LDSM_X4(afr[mi], sA + r * 128 + ((kb + aColB) ^ ((r & 7) << 4)));
            }
            uint32_t bfr[2][4];
#pragma unroll
            for (int p = 0; p < 2; p++) {
                uint32_t r = bRow + (uint32_t)p * 16;
                LDSM_X4(bfr[p], sB + r * 128 + ((kb + bColB) ^ ((r & 7) << 4)));
            }
#pragma unroll
            for (int mi = 0; mi < 4; mi++) {
#pragma unroll
                for (int p = 0; p < 2; p++) {
                    mma_f16(acc[mi][2 * p],     afr[mi], bfr[p][0], bfr[p][1]);
                    mma_f16(acc[mi][2 * p + 1], afr[mi], bfr[p][2], bfr[p][3]);
                }
            }
        }
    }
    CP_WAIT0();

    // ---- epilogue: tanh(acc + proj_h + b1) . V, reduce over BN ----
#pragma unroll
    for (int mi = 0; mi < 4; mi++) {
        float sum0 = 0.f, sum1 = 0.f;
#pragma unroll
        for (int ni = 0; ni < 4; ni++) {
            int c = wn * 32 + ni * 8 + 2 * (lane & 3);
            float add0 = s_add[c], add1 = s_add[c + 1];
            float v0 = s_v[c], v1 = s_v[c + 1];
            sum0 += v0 * tanh_fast(acc[mi][ni][0] + add0) + v1 * tanh_fast(acc[mi][ni][1] + add1);
            sum1 += v0 * tanh_fast(acc[mi][ni][2] + add0) + v1 * tanh_fast(acc[mi][ni][3] + add1);
        }
        sum0 += __shfl_xor_sync(0xffffffff, sum0, 1);
        sum0 += __shfl_xor_sync(0xffffffff, sum0, 2);
        sum1 += __shfl_xor_sync(0xffffffff, sum1, 1);
        sum1 += __shfl_xor_sync(0xffffffff, sum1, 2);
        if ((lane & 3) == 0) {
            int r = wm * 64 + mi * 16 + (lane >> 2);
            s_red[wn][r]     = sum0;
            s_red[wn][r + 8] = sum1;
        }
    }
    __syncthreads();
    if (tid < BM) {
        float part = ((s_red[0][tid] + s_red[1][tid]) + (s_red[2][tid] + s_red[3][tid])) +
                     ((s_red[4][tid] + s_red[5][tid]) + (s_red[6][tid] + s_red[7][tid]));
        g_partial[(row0 + tid) * NTILES + ntile] = part;
    }
}

// ---------------------------------------------------------------------------
// 4) Softmax over L per batch
// ---------------------------------------------------------------------------
__global__ __launch_bounds__(256) void softmax_kernel(const float* __restrict__ bV,
                                                      float* __restrict__ out_w) {
    __shared__ float sl[LEN];
    __shared__ float sred[256];
    int b = blockIdx.x, tid = threadIdx.x;
    float bv = bV[0];
    float lmax = -1e30f;
    for (int i = tid; i < LEN; i += 256) {
        const float* p = g_partial + (size_t)(b * LEN + i) * NTILES;
        float s = (p[0] + p[1]) + (p[2] + p[3]) + bv;
        sl[i] = s;
        lmax = fmaxf(lmax, s);
    }
    sred[tid] = lmax;
    __syncthreads();
    for (int s = 128; s > 0; s >>= 1) {
        if (tid < s) sred[tid] = fmaxf(sred[tid], sred[tid + s]);
        __syncthreads();
    }
    float mx = sred[0];
    __syncthreads();
    float lsum = 0.f;
    for (int i = tid; i < LEN; i += 256) {
        float e = expf(sl[i] - mx);
        sl[i] = e;
        lsum += e;
    }
    sred[tid] = lsum;
    __syncthreads();
    for (int s = 128; s > 0; s >>= 1) {
        if (tid < s) sred[tid] += sred[tid + s];
        __syncthreads();
    }
    float inv = 1.0f / sred[0];
    for (int i = tid; i < LEN; i += 256)
        out_w[(size_t)b * LEN + i] = sl[i] * inv;
}

// ---------------------------------------------------------------------------
// 5) context[b][d] = sum_l w[b][l] * features[b][l][d]   (fp32 features)
// ---------------------------------------------------------------------------
__global__ __launch_bounds__(256) void context_kernel(const float* __restrict__ features,
                                                      const float* __restrict__ w,
                                                      float* __restrict__ out) {
    __shared__ float sw[LEN];
    int b = blockIdx.y, chunk = blockIdx.x, tid = threadIdx.x;
    for (int i = tid; i < LEN; i += 256) sw[i] = w[(size_t)b * LEN + i];
    __syncthreads();
    int d = chunk * 256 + tid;
    const float* f = features + (size_t)b * LEN * DIM + d;
    float a0 = 0.f, a1 = 0.f, a2 = 0.f, a3 = 0.f;
    for (int l = 0; l < LEN; l += 4) {
        a0 += sw[l]     * f[(size_t)l * DIM];
        a1 += sw[l + 1] * f[(size_t)(l + 1) * DIM];
        a2 += sw[l + 2] * f[(size_t)(l + 2) * DIM];
        a3 += sw[l + 3] * f[(size_t)(l + 3) * DIM];
    }
    out[(size_t)b * DIM + d] = (a0 + a1) + (a2 + a3);
}

// ---------------------------------------------------------------------------
extern "C" void kernel_launch(void* const* d_in, const int* in_sizes, int n_in,
                              void* d_out, int out_size) {
    const float* features = (const float*)d_in[0];
    const float* hidden   = (const float*)d_in[1];
    const float* W1       = (const float*)d_in[2];
    const float* b1       = (const float*)d_in[3];
    const float* W2       = (const float*)d_in[4];
    const float* b2       = (const float*)d_in[5];
    const float* V        = (const float*)d_in[6];
    const float* bV       = (const float*)d_in[7];

    float* out_ctx = (float*)d_out;                 // [B, D]
    float* out_w   = (float*)d_out + BATCH * DIM;   // [B, L, 1]

    static bool attr_set = false;
    if (!attr_set) {
        cudaFuncSetAttribute(fused_gemm_f16, cudaFuncAttributeMaxDynamicSharedMemorySize, DYN_SMEM);
        attr_set = true;
    }

    conv_feat_kernel<<<(MROWS * (DIM / 8)) / 256, 256>>>(features);   // 32768 blocks
    prep_w1_kernel<<<dim3(32, 32), dim3(32, 8)>>>(W1);
    projh_kernel<<<UNITS / 64, 512>>>(hidden, W2, b2);
    fused_gemm_f16<<<dim3(NTILES, MROWS / BM), 512, DYN_SMEM>>>(b1, V);
    softmax_kernel<<<BATCH, 256>>>(bV, out_w);
    context_kernel<<<dim3(DIM / 256, BATCH), 256>>>(features, out_w, out_ctx);
}

// round 13
// speedup vs baseline: 2.1891x; 1.0034x over previous
#include <cuda_runtime.h>
#include <cuda_fp16.h>
#include <cstdint>
#include <math.h>

// Problem shape (fixed)
#define BATCH 64
#define LEN   1024
#define DIM   1024
#define HID   1024
#define UNITS 1024
#define MROWS (BATCH * LEN)   // 65536

// fp16 GEMM tiling (mma.sync m16n8k16 f16)
#define BM 128
#define BN 256
#define BKH 64                // halves per k-chunk = 128 bytes/row
#define KT (DIM / BKH)        // 16
#define NTILES (UNITS / BN)   // 4
#define STAGES 4
#define STAGE_A_BYTES (BM * 128)                       // 16384
#define STAGE_B_BYTES (BN * 128)                       // 32768
#define STAGE_BYTES   (STAGE_A_BYTES + STAGE_B_BYTES)  // 49152
#define DYN_SMEM (STAGES * STAGE_BYTES)                // 196608

// Scratch (__device__ globals; no allocation allowed)
__device__ __half g_feat_h[(size_t)MROWS * DIM];    // features in fp16 (128 MB)
__device__ __half g_w1t_h[(size_t)UNITS * DIM];     // W1 transposed [u][d], fp16
__device__ float  g_projh[BATCH * UNITS];           // hidden @ W2 + b2
__device__ float  g_partial[(size_t)MROWS * NTILES];// partial logits per (row, ntile)

// ---------------------------------------------------------------------------
// helpers
// ---------------------------------------------------------------------------
__device__ __forceinline__ uint32_t smem_u32(const void* p) {
    uint32_t a;
    asm("{ .reg .u64 t; cvta.to.shared.u64 t, %1; cvt.u32.u64 %0, t; }" : "=r"(a) : "l"(p));
    return a;
}

__device__ __forceinline__ uint32_t h2_as_u32(__half2 h) {
    return *reinterpret_cast<uint32_t*>(&h);
}

#define CP_ASYNC16(dst, src) \
    asm volatile("cp.async.cg.shared.global [%0], [%1], 16;" :: "r"(dst), "l"(src))
#define CP_COMMIT() asm volatile("cp.async.commit_group;" ::: "memory")
#define CP_WAIT2()  asm volatile("cp.async.wait_group 2;" ::: "memory")
#define CP_WAIT0()  asm volatile("cp.async.wait_group 0;" ::: "memory")

#define LDSM_X4(r, addr)                                                        \
    asm volatile("ldmatrix.sync.aligned.m8n8.x4.shared.b16 {%0,%1,%2,%3}, [%4];" \
                 : "=r"((r)[0]), "=r"((r)[1]), "=r"((r)[2]), "=r"((r)[3])        \
                 : "r"(addr))

__device__ __forceinline__ void mma_f16(float c[4], const uint32_t a[4],
                                        uint32_t b0, uint32_t b1) {
    asm volatile(
        "mma.sync.aligned.m16n8k16.row.col.f32.f16.f16.f32 "
        "{%0,%1,%2,%3}, {%4,%5,%6,%7}, {%8,%9}, {%0,%1,%2,%3};\n"
        : "+f"(c[0]), "+f"(c[1]), "+f"(c[2]), "+f"(c[3])
        : "r"(a[0]), "r"(a[1]), "r"(a[2]), "r"(a[3]), "r"(b0), "r"(b1));
}

__device__ __forceinline__ float tanh_fast(float x) {
    float e = __expf(2.0f * x);
    return 1.0f - __fdividef(2.0f, e + 1.0f);
}

// ---------------------------------------------------------------------------
// 0) Convert features fp32 -> fp16 (rn). 8 floats per thread.
// ---------------------------------------------------------------------------
__global__ __launch_bounds__(256) void conv_feat_kernel(const float* __restrict__ features) {
    size_t i = ((size_t)blockIdx.x * 256 + threadIdx.x) * 8;
    float4 v0 = *(const float4*)(features + i);
    float4 v1 = *(const float4*)(features + i + 4);
    uint4 out;
    out.x = h2_as_u32(__floats2half2_rn(v0.x, v0.y));
    out.y = h2_as_u32(__floats2half2_rn(v0.z, v0.w));
    out.z = h2_as_u32(__floats2half2_rn(v1.x, v1.y));
    out.w = h2_as_u32(__floats2half2_rn(v1.z, v1.w));
    *(uint4*)(g_feat_h + i) = out;
}

// ---------------------------------------------------------------------------
// 1) Transpose W1 [D][U] -> g_w1t_h [U][D], fp16 (rn)
// ---------------------------------------------------------------------------
__global__ void prep_w1_kernel(const float* __restrict__ W1) {
    __shared__ float tile[32][33];
    int u = blockIdx.x * 32 + threadIdx.x;
    int d0 = blockIdx.y * 32;
#pragma unroll
    for (int j = 0; j < 32; j += 8)
        tile[threadIdx.y + j][threadIdx.x] = W1[(size_t)(d0 + threadIdx.y + j) * UNITS + u];
    __syncthreads();
    int dd = d0 + threadIdx.x;
    int u0 = blockIdx.x * 32;
#pragma unroll
    for (int j = 0; j < 32; j += 8)
        g_w1t_h[(size_t)(u0 + threadIdx.y + j) * DIM + dd] =
            __float2half_rn(tile[threadIdx.x][threadIdx.y + j]);
}

// ---------------------------------------------------------------------------
// 2) proj_h = hidden @ W2 + b2 — tiled so W2 is read exactly once (fp32 exact)
// ---------------------------------------------------------------------------
__global__ __launch_bounds__(512) void projh_kernel(const float* __restrict__ hidden,
                                                    const float* __restrict__ W2,
                                                    const float* __restrict__ b2) {
    __shared__ float sh[64][65];
    __shared__ float sw[64][65];
    const int tid = threadIdx.x;
    const int u0 = blockIdx.x * 64;
    const int uu = tid & 63;
    const int bb = (tid >> 6) * 8;
    float acc[8] = {0.f, 0.f, 0.f, 0.f, 0.f, 0.f, 0.f, 0.f};

    for (int hc = 0; hc < HID / 64; hc++) {
        const int h0 = hc * 64;
#pragma unroll
        for (int i = 0; i < 8; i++) {
            int idx = tid + i * 512;
            int b = idx >> 6, h = idx & 63;
            sh[b][h] = hidden[(size_t)b * HID + h0 + h];
        }
#pragma unroll
        for (int i = 0; i < 8; i++) {
            int idx = tid + i * 512;
            int h = idx >> 6, u = idx & 63;
            sw[h][u] = W2[(size_t)(h0 + h) * UNITS + u0 + u];
        }
        __syncthreads();
#pragma unroll 16
        for (int h = 0; h < 64; h++) {
            float w = sw[h][uu];
#pragma unroll
            for (int j = 0; j < 8; j++)
                acc[j] += sh[bb + j][h] * w;
        }
        __syncthreads();
    }
    float bias = b2[u0 + uu];
#pragma unroll
    for (int j = 0; j < 8; j++)
        g_projh[(size_t)(bb + j) * UNITS + u0 + uu] = acc[j] + bias;
}

// ---------------------------------------------------------------------------
// 3) Fused fp16 GEMM: cp.async 4-stage, single barrier/iter
//    grid (NTILES, MROWS/BM) = (4, 512); 256 threads = 8 warps (2m x 4n)
//    warp tile 64x64 (128 acc regs) -> LDSM traffic 128KB/chunk (was 192KB)
// ---------------------------------------------------------------------------
__global__ __launch_bounds__(256, 1) void fused_gemm_f16(const float* __restrict__ b1,
                                                         const float* __restrict__ V) {
    extern __shared__ char dsmem_raw[];
    __shared__ float s_red[4][BM];
    __shared__ float s_add[BN];
    __shared__ float s_v[BN];

    const int tid  = threadIdx.x;
    const int lane = tid & 31;
    const int warp = tid >> 5;          // 0..7
    const int wm   = warp >> 2;         // 0..1
    const int wn   = warp & 3;          // 0..3
    const int ntile = blockIdx.x;
    const int mtile = blockIdx.y;
    const size_t row0 = (size_t)mtile * BM;
    const int u0 = ntile * BN;
    const int b = mtile >> 3;           // LEN/BM = 8 m-tiles per batch

    const uint32_t smem0 = smem_u32(dsmem_raw);

    s_add[tid] = g_projh[(size_t)b * UNITS + u0 + tid] + b1[u0 + tid];
    s_v[tid]   = V[u0 + tid];

    float acc[4][8][4];
#pragma unroll
    for (int mi = 0; mi < 4; mi++)
#pragma unroll
        for (int ni = 0; ni < 8; ni++)
#pragma unroll
            for (int j = 0; j < 4; j++) acc[mi][ni][j] = 0.f;

    const __half* Ag = g_feat_h + row0 * DIM;
    const __half* Bg = g_w1t_h + (size_t)u0 * DIM;

    // loader constants (256 threads, 8 threads/row of 128B, 16B each)
    const int lrow  = tid >> 3;                // 0..31
    const int lcolh = (tid & 7) * 8;           // half-index within row
    const uint32_t lsw = ((uint32_t)(tid & 7) * 16) ^ ((uint32_t)(lrow & 7) << 4);

    // ldmatrix per-lane constants (b16 fragments, 128B rows)
    const uint32_t aRow  = (uint32_t)(wm * 64 + (lane & 7) + ((lane >> 3) & 1) * 8);
    const uint32_t aColB = (uint32_t)(lane >> 4) * 16;
    const uint32_t bRow  = (uint32_t)(wn * 64 + (lane & 7) + (lane >> 4) * 8);
    const uint32_t bColB = (uint32_t)((lane >> 3) & 1) * 16;

    auto load_stage = [&](int itL, int slot) {
        const uint32_t sA = smem0 + slot * STAGE_BYTES;
        const uint32_t sB = sA + STAGE_A_BYTES;
        const int k0 = itL * BKH;
#pragma unroll
        for (int p = 0; p < 4; p++) {          // A: 128 rows
            int r = lrow + p * 32;
            CP_ASYNC16(sA + (uint32_t)r * 128 + lsw, Ag + (size_t)r * DIM + k0 + lcolh);
        }
#pragma unroll
        for (int p = 0; p < 8; p++) {          // B: 256 rows
            int r = lrow + p * 32;
            CP_ASYNC16(sB + (uint32_t)r * 128 + lsw, Bg + (size_t)r * DIM + k0 + lcolh);
        }
    };

    load_stage(0, 0); CP_COMMIT();
    load_stage(1, 1); CP_COMMIT();
    load_stage(2, 2); CP_COMMIT();

#pragma unroll 1
    for (int it = 0; it < KT; it++) {
        CP_WAIT2();          // stage `it` resident
        __syncthreads();

        const int ls = it + STAGES - 1;
        if (ls < KT) load_stage(ls, ls & (STAGES - 1));
        CP_COMMIT();         // uniform group counting

        const uint32_t sA = smem0 + (it & (STAGES - 1)) * STAGE_BYTES;
        const uint32_t sB = sA + STAGE_A_BYTES;
#pragma unroll
        for (int ks = 0; ks < 4; ks++) {       // k16 per step, 64 per chunk
            const uint32_t kb = (uint32_t)(ks * 32);  // byte offset of k-step
            uint32_t afr[4][4];
#pragma unroll
            for (int mi = 0; mi < 4; mi++) {
                uint32_t r = aRow + (uint32_t)mi * 16;
                LDSM_X4(afr[mi], sA + r * 128 + ((kb + aColB) ^ ((r & 7) << 4)));
            }
            uint32_t bfr[4][4];
#pragma unroll
            for (int p = 0; p < 4; p++) {
                uint32_t r = bRow + (uint32_t)p * 16;
                LDSM_X4(bfr[p], sB + r * 128 + ((kb + bColB) ^ ((r & 7) << 4)));
            }
#pragma unroll
            for (int mi = 0; mi < 4; mi++) {
#pragma unroll
                for (int p = 0; p < 4; p++) {
                    mma_f16(acc[mi][2 * p],     afr[mi], bfr[p][0], bfr[p][1]);
                    mma_f16(acc[mi][2 * p + 1], afr[mi], bfr[p][2], bfr[p][3]);
                }
            }
        }
    }
    CP_WAIT0();

    // ---- epilogue: tanh(acc + proj_h + b1) . V, reduce over BN ----
#pragma unroll
    for (int mi = 0; mi < 4; mi++) {
        float sum0 = 0.f, sum1 = 0.f;
#pragma unroll
        for (int ni = 0; ni < 8; ni++) {
            int c = wn * 64 + ni * 8 + 2 * (lane & 3);
            float add0 = s_add[c], add1 = s_add[c + 1];
            float v0 = s_v[c], v1 = s_v[c + 1];
            sum0 += v0 * tanh_fast(acc[mi][ni][0] + add0) + v1 * tanh_fast(acc[mi][ni][1] + add1);
            sum1 += v0 * tanh_fast(acc[mi][ni][2] + add0) + v1 * tanh_fast(acc[mi][ni][3] + add1);
        }
        sum0 += __shfl_xor_sync(0xffffffff, sum0, 1);
        sum0 += __shfl_xor_sync(0xffffffff, sum0, 2);
        sum1 += __shfl_xor_sync(0xffffffff, sum1, 1);
        sum1 += __shfl_xor_sync(0xffffffff, sum1, 2);
        if ((lane & 3) == 0) {
            int r = wm * 64 + mi * 16 + (lane >> 2);
            s_red[wn][r]     = sum0;
            s_red[wn][r + 8] = sum1;
        }
    }
    __syncthreads();
    if (tid < BM) {
        float part = (s_red[0][tid] + s_red[1][tid]) + (s_red[2][tid] + s_red[3][tid]);
        g_partial[(row0 + tid) * NTILES + ntile] = part;
    }
}

// ---------------------------------------------------------------------------
// 4) Softmax over L per batch
// ---------------------------------------------------------------------------
__global__ __launch_bounds__(256) void softmax_kernel(const float* __restrict__ bV,
                                                      float* __restrict__ out_w) {
    __shared__ float sl[LEN];
    __shared__ float sred[256];
    int b = blockIdx.x, tid = threadIdx.x;
    float bv = bV[0];
    float lmax = -1e30f;
    for (int i = tid; i < LEN; i += 256) {
        const float* p = g_partial + (size_t)(b * LEN + i) * NTILES;
        float s = (p[0] + p[1]) + (p[2] + p[3]) + bv;
        sl[i] = s;
        lmax = fmaxf(lmax, s);
    }
    sred[tid] = lmax;
    __syncthreads();
    for (int s = 128; s > 0; s >>= 1) {
        if (tid < s) sred[tid] = fmaxf(sred[tid], sred[tid + s]);
        __syncthreads();
    }
    float mx = sred[0];
    __syncthreads();
    float lsum = 0.f;
    for (int i = tid; i < LEN; i += 256) {
        float e = expf(sl[i] - mx);
        sl[i] = e;
        lsum += e;
    }
    sred[tid] = lsum;
    __syncthreads();
    for (int s = 128; s > 0; s >>= 1) {
        if (tid < s) sred[tid] += sred[tid + s];
        __syncthreads();
    }
    float inv = 1.0f / sred[0];
    for (int i = tid; i < LEN; i += 256)
        out_w[(size_t)b * LEN + i] = sl[i] * inv;
}

// ---------------------------------------------------------------------------
// 5) context[b][d] = sum_l w[b][l] * features[b][l][d]  (fp16 features, half2)
// ---------------------------------------------------------------------------
__global__ __launch_bounds__(256) void context_kernel(const float* __restrict__ w,
                                                      float* __restrict__ out) {
    __shared__ float sw[LEN];
    int b = blockIdx.y, chunk = blockIdx.x, tid = threadIdx.x;
    for (int i = tid; i < LEN; i += 256) sw[i] = w[(size_t)b * LEN + i];
    __syncthreads();
    int d = (chunk * 256 + tid) * 2;
    const __half2* f = (const __half2*)(g_feat_h + (size_t)b * LEN * DIM + d);
    float ax0 = 0.f, ay0 = 0.f, ax1 = 0.f, ay1 = 0.f;
    for (int l = 0; l < LEN; l += 2) {
        float2 v0 = __half22float2(f[(size_t)l * (DIM / 2)]);
        float2 v1 = __half22float2(f[(size_t)(l + 1) * (DIM / 2)]);
        ax0 += sw[l] * v0.x;     ay0 += sw[l] * v0.y;
        ax1 += sw[l + 1] * v1.x; ay1 += sw[l + 1] * v1.y;
    }
    out[(size_t)b * DIM + d]     = ax0 + ax1;
    out[(size_t)b * DIM + d + 1] = ay0 + ay1;
}

// ---------------------------------------------------------------------------
extern "C" void kernel_launch(void* const* d_in, const int* in_sizes, int n_in,
                              void* d_out, int out_size) {
    const float* features = (const float*)d_in[0];
    const float* hidden   = (const float*)d_in[1];
    const float* W1       = (const float*)d_in[2];
    const float* b1       = (const float*)d_in[3];
    const float* W2       = (const float*)d_in[4];
    const float* b2       = (const float*)d_in[5];
    const float* V        = (const float*)d_in[6];
    const float* bV       = (const float*)d_in[7];

    float* out_ctx = (float*)d_out;                 // [B, D]
    float* out_w   = (float*)d_out + BATCH * DIM;   // [B, L, 1]

    static bool attr_set = false;
    if (!attr_set) {
        cudaFuncSetAttribute(fused_gemm_f16, cudaFuncAttributeMaxDynamicSharedMemorySize, DYN_SMEM);
        attr_set = true;
    }

    conv_feat_kernel<<<(MROWS * (DIM / 8)) / 256, 256>>>(features);
    prep_w1_kernel<<<dim3(32, 32), dim3(32, 8)>>>(W1);
    projh_kernel<<<UNITS / 64, 512>>>(hidden, W2, b2);
    fused_gemm_f16<<<dim3(NTILES, MROWS / BM), 256, DYN_SMEM>>>(b1, V);
    softmax_kernel<<<BATCH, 256>>>(bV, out_w);
    context_kernel<<<dim3(DIM / 512, BATCH), 256>>>(out_w, out_ctx);
}

// round 15
// speedup vs baseline: 2.3712x; 1.0832x over previous
#include <cuda_runtime.h>
#include <cuda_fp16.h>
#include <cstdint>
#include <math.h>

// Problem shape (fixed)
#define BATCH 64
#define LEN   1024
#define DIM   1024
#define HID   1024
#define UNITS 1024
#define MROWS (BATCH * LEN)   // 65536

// fp16 GEMM tiling (mma.sync m16n8k16 f16)
#define BM 128
#define BN 128
#define BKH 64                // halves per k-chunk = 128 bytes/row
#define KT (DIM / BKH)        // 16
#define NTILES (UNITS / BN)   // 8
#define STAGES 3
#define STAGE_A_BYTES (BM * 128)                       // 16384
#define STAGE_B_BYTES (BN * 128)                       // 16384
#define STAGE_BYTES   (STAGE_A_BYTES + STAGE_B_BYTES)  // 32768
#define DYN_SMEM (STAGES * STAGE_BYTES)                // 98304

// Scratch (__device__ globals; no allocation allowed)
__device__ __half g_feat_h[(size_t)MROWS * DIM];    // features in fp16 (128 MB)
__device__ __half g_w1t_h[(size_t)UNITS * DIM];     // W1 transposed [u][d], fp16
__device__ float  g_projh[BATCH * UNITS];           // hidden @ W2 + b2
__device__ float  g_partial[(size_t)MROWS * NTILES];// partial logits per (row, ntile)

// ---------------------------------------------------------------------------
// helpers
// ---------------------------------------------------------------------------
__device__ __forceinline__ uint32_t smem_u32(const void* p) {
    uint32_t a;
    asm("{ .reg .u64 t; cvta.to.shared.u64 t, %1; cvt.u32.u64 %0, t; }" : "=r"(a) : "l"(p));
    return a;
}

__device__ __forceinline__ uint32_t h2_as_u32(__half2 h) {
    return *reinterpret_cast<uint32_t*>(&h);
}

#define CP_ASYNC16(dst, src) \
    asm volatile("cp.async.cg.shared.global [%0], [%1], 16;" :: "r"(dst), "l"(src))
#define CP_COMMIT() asm volatile("cp.async.commit_group;" ::: "memory")
#define CP_WAIT1()  asm volatile("cp.async.wait_group 1;" ::: "memory")
#define CP_WAIT0()  asm volatile("cp.async.wait_group 0;" ::: "memory")

#define LDSM_X4(r, addr)                                                        \
    asm volatile("ldmatrix.sync.aligned.m8n8.x4.shared.b16 {%0,%1,%2,%3}, [%4];" \
                 : "=r"((r)[0]), "=r"((r)[1]), "=r"((r)[2]), "=r"((r)[3])        \
                 : "r"(addr))

__device__ __forceinline__ void mma_f16(float c[4], const uint32_t a[4],
                                        uint32_t b0, uint32_t b1) {
    asm volatile(
        "mma.sync.aligned.m16n8k16.row.col.f32.f16.f16.f32 "
        "{%0,%1,%2,%3}, {%4,%5,%6,%7}, {%8,%9}, {%0,%1,%2,%3};\n"
        : "+f"(c[0]), "+f"(c[1]), "+f"(c[2]), "+f"(c[3])
        : "r"(a[0]), "r"(a[1]), "r"(a[2]), "r"(a[3]), "r"(b0), "r"(b1));
}

__device__ __forceinline__ float tanh_fast(float x) {
    float e = __expf(2.0f * x);
    return 1.0f - __fdividef(2.0f, e + 1.0f);
}

// ---------------------------------------------------------------------------
// 0) Convert features fp32 -> fp16 (rn). 8 floats per thread.
// ---------------------------------------------------------------------------
__global__ __launch_bounds__(256) void conv_feat_kernel(const float* __restrict__ features) {
    size_t i = ((size_t)blockIdx.x * 256 + threadIdx.x) * 8;
    float4 v0 = *(const float4*)(features + i);
    float4 v1 = *(const float4*)(features + i + 4);
    uint4 out;
    out.x = h2_as_u32(__floats2half2_rn(v0.x, v0.y));
    out.y = h2_as_u32(__floats2half2_rn(v0.z, v0.w));
    out.z = h2_as_u32(__floats2half2_rn(v1.x, v1.y));
    out.w = h2_as_u32(__floats2half2_rn(v1.z, v1.w));
    *(uint4*)(g_feat_h + i) = out;
}

// ---------------------------------------------------------------------------
// 1) Transpose W1 [D][U] -> g_w1t_h [U][D], fp16 (rn)
// ---------------------------------------------------------------------------
__global__ void prep_w1_kernel(const float* __restrict__ W1) {
    __shared__ float tile[32][33];
    int u = blockIdx.x * 32 + threadIdx.x;
    int d0 = blockIdx.y * 32;
#pragma unroll
    for (int j = 0; j < 32; j += 8)
        tile[threadIdx.y + j][threadIdx.x] = W1[(size_t)(d0 + threadIdx.y + j) * UNITS + u];
    __syncthreads();
    int dd = d0 + threadIdx.x;
    int u0 = blockIdx.x * 32;
#pragma unroll
    for (int j = 0; j < 32; j += 8)
        g_w1t_h[(size_t)(u0 + threadIdx.y + j) * DIM + dd] =
            __float2half_rn(tile[threadIdx.x][threadIdx.y + j]);
}

// ---------------------------------------------------------------------------
// 2) proj_h = hidden @ W2 + b2 — tiled so W2 is read exactly once (fp32 exact)
// ---------------------------------------------------------------------------
__global__ __launch_bounds__(512) void projh_kernel(const float* __restrict__ hidden,
                                                    const float* __restrict__ W2,
                                                    const float* __restrict__ b2) {
    __shared__ float sh[64][65];
    __shared__ float sw[64][65];
    const int tid = threadIdx.x;
    const int u0 = blockIdx.x * 64;
    const int uu = tid & 63;
    const int bb = (tid >> 6) * 8;
    float acc[8] = {0.f, 0.f, 0.f, 0.f, 0.f, 0.f, 0.f, 0.f};

    for (int hc = 0; hc < HID / 64; hc++) {
        const int h0 = hc * 64;
#pragma unroll
        for (int i = 0; i < 8; i++) {
            int idx = tid + i * 512;
            int b = idx >> 6, h = idx & 63;
            sh[b][h] = hidden[(size_t)b * HID + h0 + h];
        }
#pragma unroll
        for (int i = 0; i < 8; i++) {
            int idx = tid + i * 512;
            int h = idx >> 6, u = idx & 63;
            sw[h][u] = W2[(size_t)(h0 + h) * UNITS + u0 + u];
        }
        __syncthreads();
#pragma unroll 16
        for (int h = 0; h < 64; h++) {
            float w = sw[h][uu];
#pragma unroll
            for (int j = 0; j < 8; j++)
                acc[j] += sh[bb + j][h] * w;
        }
        __syncthreads();
    }
    float bias = b2[u0 + uu];
#pragma unroll
    for (int j = 0; j < 8; j++)
        g_projh[(size_t)(bb + j) * UNITS + u0 + uu] = acc[j] + bias;
}

// ---------------------------------------------------------------------------
// 3) Fused fp16 GEMM: cp.async 3-stage, 128 threads, 2 CTAs/SM
//    grid (NTILES, MROWS/BM) = (8, 512); 4 warps (2m x 2n), warp tile 64x64
//    Two independent CTAs per SM -> LDSM of one overlaps MMA of the other
// ---------------------------------------------------------------------------
__global__ __launch_bounds__(128, 2) void fused_gemm_f16(const float* __restrict__ b1,
                                                         const float* __restrict__ V) {
    extern __shared__ char dsmem_raw[];
    __shared__ float s_red[2][BM];
    __shared__ float s_add[BN];
    __shared__ float s_v[BN];

    const int tid  = threadIdx.x;
    const int lane = tid & 31;
    const int warp = tid >> 5;          // 0..3
    const int wm   = warp >> 1;         // 0..1
    const int wn   = warp & 1;          // 0..1
    const int ntile = blockIdx.x;
    const int mtile = blockIdx.y;
    const size_t row0 = (size_t)mtile * BM;
    const int u0 = ntile * BN;
    const int b = mtile >> 3;           // LEN/BM = 8 m-tiles per batch

    const uint32_t smem0 = smem_u32(dsmem_raw);

    s_add[tid] = g_projh[(size_t)b * UNITS + u0 + tid] + b1[u0 + tid];
    s_v[tid]   = V[u0 + tid];

    float acc[4][8][4];
#pragma unroll
    for (int mi = 0; mi < 4; mi++)
#pragma unroll
        for (int ni = 0; ni < 8; ni++)
#pragma unroll
            for (int j = 0; j < 4; j++) acc[mi][ni][j] = 0.f;

    const __half* Ag = g_feat_h + row0 * DIM;
    const __half* Bg = g_w1t_h + (size_t)u0 * DIM;

    // loader constants (128 threads, 8 threads/row of 128B, 16B each)
    const int lrow  = tid >> 3;                // 0..15
    const int lcolh = (tid & 7) * 8;           // half-index within row
    const uint32_t lsw = ((uint32_t)(tid & 7) * 16) ^ ((uint32_t)(lrow & 7) << 4);

    // ldmatrix per-lane constants (b16 fragments, 128B rows)
    const uint32_t aRow  = (uint32_t)(wm * 64 + (lane & 7) + ((lane >> 3) & 1) * 8);
    const uint32_t aColB = (uint32_t)(lane >> 4) * 16;
    const uint32_t bRow  = (uint32_t)(wn * 64 + (lane & 7) + (lane >> 4) * 8);
    const uint32_t bColB = (uint32_t)((lane >> 3) & 1) * 16;

    auto load_stage = [&](int itL, int slot) {
        const uint32_t sA = smem0 + slot * STAGE_BYTES;
        const uint32_t sB = sA + STAGE_A_BYTES;
        const int k0 = itL * BKH;
#pragma unroll
        for (int p = 0; p < 8; p++) {          // A: 128 rows
            int r = lrow + p * 16;
            CP_ASYNC16(sA + (uint32_t)r * 128 + lsw, Ag + (size_t)r * DIM + k0 + lcolh);
        }
#pragma unroll
        for (int p = 0; p < 8; p++) {          // B: 128 rows
            int r = lrow + p * 16;
            CP_ASYNC16(sB + (uint32_t)r * 128 + lsw, Bg + (size_t)r * DIM + k0 + lcolh);
        }
    };

    load_stage(0, 0); CP_COMMIT();
    load_stage(1, 1); CP_COMMIT();

    int slot_mod[3];
#pragma unroll
    for (int s = 0; s < 3; s++) slot_mod[s] = s;

#pragma unroll 1
    for (int it = 0; it < KT; it++) {
        CP_WAIT1();          // stage `it` resident (<=1 newer group outstanding)
        __syncthreads();

        const int ls = it + STAGES - 1;
        const int lslot = (it + 2) % STAGES;
        if (ls < KT) load_stage(ls, lslot);
        CP_COMMIT();         // uniform group counting

        const uint32_t sA = smem0 + (it % STAGES) * STAGE_BYTES;
        const uint32_t sB = sA + STAGE_A_BYTES;
#pragma unroll
        for (int ks = 0; ks < 4; ks++) {       // k16 per step, 64 per chunk
            const uint32_t kb = (uint32_t)(ks * 32);  // byte offset of k-step
            uint32_t afr[4][4];
#pragma unroll
            for (int mi = 0; mi < 4; mi++) {
                uint32_t r = aRow + (uint32_t)mi * 16;
                LDSM_X4(afr[mi], sA + r * 128 + ((kb + aColB) ^ ((r & 7) << 4)));
            }
            uint32_t bfr[4][4];
#pragma unroll
            for (int p = 0; p < 4; p++) {
                uint32_t r = bRow + (uint32_t)p * 16;
                LDSM_X4(bfr[p], sB + r * 128 + ((kb + bColB) ^ ((r & 7) << 4)));
            }
#pragma unroll
            for (int mi = 0; mi < 4; mi++) {
#pragma unroll
                for (int p = 0; p < 4; p++) {
                    mma_f16(acc[mi][2 * p],     afr[mi], bfr[p][0], bfr[p][1]);
                    mma_f16(acc[mi][2 * p + 1], afr[mi], bfr[p][2], bfr[p][3]);
                }
            }
        }
    }
    CP_WAIT0();

    // ---- epilogue: tanh(acc + proj_h + b1) . V, reduce over BN ----
#pragma unroll
    for (int mi = 0; mi < 4; mi++) {
        float sum0 = 0.f, sum1 = 0.f;
#pragma unroll
        for (int ni = 0; ni < 8; ni++) {
            int c = wn * 64 + ni * 8 + 2 * (lane & 3);
            float add0 = s_add[c], add1 = s_add[c + 1];
            float v0 = s_v[c], v1 = s_v[c + 1];
            sum0 += v0 * tanh_fast(acc[mi][ni][0] + add0) + v1 * tanh_fast(acc[mi][ni][1] + add1);
            sum1 += v0 * tanh_fast(acc[mi][ni][2] + add0) + v1 * tanh_fast(acc[mi][ni][3] + add1);
        }
        sum0 += __shfl_xor_sync(0xffffffff, sum0, 1);
        sum0 += __shfl_xor_sync(0xffffffff, sum0, 2);
        sum1 += __shfl_xor_sync(0xffffffff, sum1, 1);
        sum1 += __shfl_xor_sync(0xffffffff, sum1, 2);
        if ((lane & 3) == 0) {
            int r = wm * 64 + mi * 16 + (lane >> 2);
            s_red[wn][r]     = sum0;
            s_red[wn][r + 8] = sum1;
        }
    }
    __syncthreads();
    if (tid < BM) {
        float part = s_red[0][tid] + s_red[1][tid];
        g_partial[(row0 + tid) * NTILES + ntile] = part;
    }
}

// ---------------------------------------------------------------------------
// 4) Softmax over L per batch (8 partials per row now)
// ---------------------------------------------------------------------------
__global__ __launch_bounds__(256) void softmax_kernel(const float* __restrict__ bV,
                                                      float* __restrict__ out_w) {
    __shared__ float sl[LEN];
    __shared__ float sred[256];
    int b = blockIdx.x, tid = threadIdx.x;
    float bv = bV[0];
    float lmax = -1e30f;
    for (int i = tid; i < LEN; i += 256) {
        const float* p = g_partial + (size_t)(b * LEN + i) * NTILES;
        float s = ((p[0] + p[1]) + (p[2] + p[3])) + ((p[4] + p[5]) + (p[6] + p[7])) + bv;
        sl[i] = s;
        lmax = fmaxf(lmax, s);
    }
    sred[tid] = lmax;
    __syncthreads();
    for (int s = 128; s > 0; s >>= 1) {
        if (tid < s) sred[tid] = fmaxf(sred[tid], sred[tid + s]);
        __syncthreads();
    }
    float mx = sred[0];
    __syncthreads();
    float lsum = 0.f;
    for (int i = tid; i < LEN; i += 256) {
        float e = expf(sl[i] - mx);
        sl[i] = e;
        lsum += e;
    }
    sred[tid] = lsum;
    __syncthreads();
    for (int s = 128; s > 0; s >>= 1) {
        if (tid < s) sred[tid] += sred[tid + s];
        __syncthreads();
    }
    float inv = 1.0f / sred[0];
    for (int i = tid; i < LEN; i += 256)
        out_w[(size_t)b * LEN + i] = sl[i] * inv;
}

// ---------------------------------------------------------------------------
// 5) context[b][d] = sum_l w[b][l] * features[b][l][d]  (fp16 features, half2)
// ---------------------------------------------------------------------------
__global__ __launch_bounds__(256) void context_kernel(const float* __restrict__ w,
                                                      float* __restrict__ out) {
    __shared__ float sw[LEN];
    int b = blockIdx.y, chunk = blockIdx.x, tid = threadIdx.x;
    for (int i = tid; i < LEN; i += 256) sw[i] = w[(size_t)b * LEN + i];
    __syncthreads();
    int d = (chunk * 256 + tid) * 2;
    const __half2* f = (const __half2*)(g_feat_h + (size_t)b * LEN * DIM + d);
    float ax0 = 0.f, ay0 = 0.f, ax1 = 0.f, ay1 = 0.f;
    for (int l = 0; l < LEN; l += 2) {
        float2 v0 = __half22float2(f[(size_t)l * (DIM / 2)]);
        float2 v1 = __half22float2(f[(size_t)(l + 1) * (DIM / 2)]);
        ax0 += sw[l] * v0.x;     ay0 += sw[l] * v0.y;
        ax1 += sw[l + 1] * v1.x; ay1 += sw[l + 1] * v1.y;
    }
    out[(size_t)b * DIM + d]     = ax0 + ax1;
    out[(size_t)b * DIM + d + 1] = ay0 + ay1;
}

// ---------------------------------------------------------------------------
extern "C" void kernel_launch(void* const* d_in, const int* in_sizes, int n_in,
                              void* d_out, int out_size) {
    const float* features = (const float*)d_in[0];
    const float* hidden   = (const float*)d_in[1];
    const float* W1       = (const float*)d_in[2];
    const float* b1       = (const float*)d_in[3];
    const float* W2       = (const float*)d_in[4];
    const float* b2       = (const float*)d_in[5];
    const float* V        = (const float*)d_in[6];
    const float* bV       = (const float*)d_in[7];

    float* out_ctx = (float*)d_out;                 // [B, D]
    float* out_w   = (float*)d_out + BATCH * DIM;   // [B, L, 1]

    static bool attr_set = false;
    if (!attr_set) {
        cudaFuncSetAttribute(fused_gemm_f16, cudaFuncAttributeMaxDynamicSharedMemorySize, DYN_SMEM);
        attr_set = true;
    }

    conv_feat_kernel<<<(MROWS * (DIM / 8)) / 256, 256>>>(features);
    prep_w1_kernel<<<dim3(32, 32), dim3(32, 8)>>>(W1);
    projh_kernel<<<UNITS / 64, 512>>>(hidden, W2, b2);
    fused_gemm_f16<<<dim3(NTILES, MROWS / BM), 128, DYN_SMEM>>>(b1, V);
    softmax_kernel<<<BATCH, 256>>>(bV, out_w);
    context_kernel<<<dim3(DIM / 512, BATCH), 256>>>(out_w, out_ctx);
}